// round 8
// baseline (speedup 1.0000x reference)
#include <cuda_runtime.h>
#include <math.h>

// WindowAttention: B=32, 64x64, C=256, ws=8 -> 2048 windows of 64 tokens.
// One CTA (256 threads) per window. fp32 FFMA2 with:
//  - pair-interleaved A-side smem layouts (LDS.64 operands, STS.64 epilogues)
//  - double-buffered smem weight tiles (kills hot-loop LDG pressure)
//  - q-scale folded into prepped weights.

#define EPS 1e-5f

__device__ float g_Wt[256 * 768];    // Wt[k][col] = w_in[col][k] * g_branch[k] (*invsqd for q cols)
__device__ float g_bias[768];
__device__ float g_WoT[256 * 256];   // WoT[k][j] = w_out[j][k]

typedef unsigned long long u64;

__device__ __forceinline__ u64 pk2(float lo, float hi) {
    u64 r; asm("mov.b64 %0, {%1, %2};" : "=l"(r) : "f"(lo), "f"(hi)); return r;
}
__device__ __forceinline__ void upk2(u64 v, float& lo, float& hi) {
    asm("mov.b64 {%0, %1}, %2;" : "=f"(lo), "=f"(hi) : "l"(v));
}
__device__ __forceinline__ void fma2(u64& d, u64 a, u64 b) {
    asm("fma.rn.f32x2 %0, %1, %2, %3;" : "=l"(d) : "l"(a), "l"(b), "l"(d));
}
__device__ __forceinline__ u64 add2(u64 a, u64 b) {
    u64 r; asm("add.rn.f32x2 %0, %1, %2;" : "=l"(r) : "l"(a), "l"(b)); return r;
}
__device__ __forceinline__ u64 lds2(const float* p) {
    return *reinterpret_cast<const u64*>(p);
}
__device__ __forceinline__ void sts2(float* p, u64 v) {
    *reinterpret_cast<u64*>(p) = v;
}

// ---- prep: fold LN affine (and q-scale) into packed in_proj, k-major ----
__global__ void prep_w_kernel(const float* __restrict__ w_in, const float* __restrict__ b_in,
                              const float* __restrict__ g_q, const float* __restrict__ b_q,
                              const float* __restrict__ g_k, const float* __restrict__ b_k,
                              const float* __restrict__ g_v, const float* __restrict__ b_v) {
    __shared__ float red[8];
    int col = blockIdx.x;       // 0..767
    int k   = threadIdx.x;      // 0..255
    const float* g; const float* b;
    if (col < 256)      { g = g_q; b = b_q; }
    else if (col < 512) { g = g_k; b = b_k; }
    else                { g = g_v; b = b_v; }
    const float f = (col < 256) ? 0.17677669529663689f : 1.0f;   // 1/sqrt(32) folded into q
    float w = w_in[col * 256 + k];
    g_Wt[k * 768 + col] = w * g[k] * f;
    float p = w * b[k];
    #pragma unroll
    for (int o = 16; o; o >>= 1) p += __shfl_xor_sync(0xffffffffu, p, o);
    if ((k & 31) == 0) red[k >> 5] = p;
    __syncthreads();
    if (k < 8) {
        float s = red[k];
        #pragma unroll
        for (int o = 4; o; o >>= 1) s += __shfl_xor_sync(0xffu, s, o);
        if (k == 0) g_bias[col] = (b_in[col] + s) * f;
    }
}

__global__ void prep_wo_kernel(const float* __restrict__ w_out) {
    int idx = blockIdx.x * 256 + threadIdx.x;   // 65536 elements
    int j = idx >> 8, k = idx & 255;
    g_WoT[k * 256 + j] = w_out[idx];
}

// ---- main fused window-attention kernel ----
// smem (floats):
//  xnp   [32][256][2]  pair-interleaved normalized input / residual   16384
//  obufp [32][256][2]  pair-interleaved attention output              16384
//  q2p   [32][65*2]    pair-interleaved q (2 heads, 64 cols, pad)      4160
//  k2    [64][65]      row-major k                                     4160
//  v2    [64][65]      row-major v                                     4160
//  scp   [32][65*2]    pair-interleaved scores                         4160
//  wbuf  double-buffered weight tiles (GEMM1: 2x1536, outproj: 2x2048) 4096
//  mA,sA [64] each                                                      128
__global__ __launch_bounds__(256, 1)
void win_attn_kernel(const float* __restrict__ x, const float* __restrict__ b_out,
                     const float* __restrict__ g_o, const float* __restrict__ b_o,
                     float* __restrict__ y) {
    extern __shared__ float sm[];
    float* xnp   = sm;             // 16384
    float* obufp = sm + 16384;     // 16384
    float* q2p   = sm + 32768;     // 4160
    float* k2    = sm + 36928;     // 4160
    float* v2    = sm + 41088;     // 4160
    float* scp   = sm + 45248;     // 4160
    float* wbuf  = sm + 49408;     // 4096
    float* mA    = sm + 53504;     // 64
    float* sA    = sm + 53568;     // 64   total 53632 floats = 214528 B

    const int tid  = threadIdx.x;
    const int w    = tid >> 5;
    const int tx   = tid & 31;
    const int row0 = w * 8;
    const int pg0  = w * 4;        // warp owns row-pairs pg0..pg0+3

    const int win = blockIdx.x;
    const int b   = win >> 6;
    const int wh  = (win >> 3) & 7;
    const int ww  = win & 7;
    const int gbase = ((b * 64 + wh * 8) * 64 + ww * 8) * 256;

    // ---- load window into pair-interleaved smem ----
    for (int t = 0; t < 64; ++t) {
        int off = gbase + (t >> 3) * (64 * 256) + (t & 7) * 256;
        xnp[(t >> 1) * 512 + tid * 2 + (t & 1)] = x[off + tid];
    }
    __syncthreads();

    // ---- LN stats + normalize in place (warp-local rows) ----
    for (int i = 0; i < 8; ++i) {
        int r = row0 + i;
        int base = (r >> 1) * 512 + (r & 1);
        float s = 0.f, ss = 0.f;
        #pragma unroll
        for (int c = tx; c < 256; c += 32) { float v = xnp[base + c * 2]; s += v; ss += v * v; }
        #pragma unroll
        for (int o = 16; o; o >>= 1) { s  += __shfl_xor_sync(0xffffffffu, s,  o);
                                       ss += __shfl_xor_sync(0xffffffffu, ss, o); }
        float mean = s * (1.f / 256.f);
        float var  = ss * (1.f / 256.f) - mean * mean;
        float sd   = sqrtf(var + EPS);
        float inv  = 1.f / sd;
        if (tx == 0) { mA[r] = mean; sA[r] = sd; }
        #pragma unroll
        for (int c = tx; c < 256; c += 32) xnp[base + c * 2] = (xnp[base + c * 2] - mean) * inv;
    }
    __syncthreads();

    for (int hp = 0; hp < 4; ++hp) {
        const int hA = hp, hB = hp + 4;
        const int cA = hA * 32 + tx, cB = hB * 32 + tx;

        // ---- GEMM1: q,k,v for heads hA,hB; weights staged in smem ----
        {
            u64 acc[4][6];
            #pragma unroll
            for (int p = 0; p < 4; ++p)
                #pragma unroll
                for (int j = 0; j < 6; ++j) acc[p][j] = 0ULL;

            // preload tile 0 (warp w stages kk row w of the tile; 6 segments)
            float st0, st1, st2, st3, st4, st5;
            {
                const float* wg = g_Wt + w * 768;
                st0 = wg[cA]; st1 = wg[256 + cA]; st2 = wg[512 + cA];
                st3 = wg[cB]; st4 = wg[256 + cB]; st5 = wg[512 + cB];
            }
            {
                float* wd = wbuf + w * 192;
                wd[tx] = st0; wd[32 + tx] = st1; wd[64 + tx] = st2;
                wd[96 + tx] = st3; wd[128 + tx] = st4; wd[160 + tx] = st5;
            }
            __syncthreads();

            const float* ap0 = xnp + (pg0 + 0) * 512;
            const float* ap1 = xnp + (pg0 + 1) * 512;
            const float* ap2 = xnp + (pg0 + 2) * 512;
            const float* ap3 = xnp + (pg0 + 3) * 512;

            for (int kt = 0; kt < 32; ++kt) {
                int cb = kt & 1, nb = cb ^ 1;
                if (kt < 31) {
                    const float* wg = g_Wt + ((kt + 1) * 8 + w) * 768;
                    st0 = wg[cA]; st1 = wg[256 + cA]; st2 = wg[512 + cA];
                    st3 = wg[cB]; st4 = wg[256 + cB]; st5 = wg[512 + cB];
                }
                const float* wt = wbuf + cb * 1536;
                #pragma unroll
                for (int kk = 0; kk < 8; ++kk) {
                    const float* wr = wt + kk * 192;
                    float w0 = wr[tx],      w1 = wr[32 + tx],  w2 = wr[64 + tx];
                    float w3 = wr[96 + tx], w4 = wr[128 + tx], w5 = wr[160 + tx];
                    u64 W0 = pk2(w0, w0), W1 = pk2(w1, w1), W2 = pk2(w2, w2);
                    u64 W3 = pk2(w3, w3), W4 = pk2(w4, w4), W5 = pk2(w5, w5);
                    const int kg2 = (kt * 8 + kk) * 2;
                    u64 A0 = lds2(ap0 + kg2), A1 = lds2(ap1 + kg2);
                    u64 A2 = lds2(ap2 + kg2), A3 = lds2(ap3 + kg2);
                    fma2(acc[0][0], A0, W0); fma2(acc[0][1], A0, W1); fma2(acc[0][2], A0, W2);
                    fma2(acc[0][3], A0, W3); fma2(acc[0][4], A0, W4); fma2(acc[0][5], A0, W5);
                    fma2(acc[1][0], A1, W0); fma2(acc[1][1], A1, W1); fma2(acc[1][2], A1, W2);
                    fma2(acc[1][3], A1, W3); fma2(acc[1][4], A1, W4); fma2(acc[1][5], A1, W5);
                    fma2(acc[2][0], A2, W0); fma2(acc[2][1], A2, W1); fma2(acc[2][2], A2, W2);
                    fma2(acc[2][3], A2, W3); fma2(acc[2][4], A2, W4); fma2(acc[2][5], A2, W5);
                    fma2(acc[3][0], A3, W0); fma2(acc[3][1], A3, W1); fma2(acc[3][2], A3, W2);
                    fma2(acc[3][3], A3, W3); fma2(acc[3][4], A3, W4); fma2(acc[3][5], A3, W5);
                }
                if (kt < 31) {
                    float* wd = wbuf + nb * 1536 + w * 192;
                    wd[tx] = st0; wd[32 + tx] = st1; wd[64 + tx] = st2;
                    wd[96 + tx] = st3; wd[128 + tx] = st4; wd[160 + tx] = st5;
                }
                __syncthreads();
            }

            // epilogue: add bias, store q (pairs), k/v (row-major)
            float bqa = g_bias[cA], bka = g_bias[256 + cA], bva = g_bias[512 + cA];
            float bqb = g_bias[cB], bkb = g_bias[256 + cB], bvb = g_bias[512 + cB];
            u64 BQA = pk2(bqa, bqa), BKA = pk2(bka, bka), BVA = pk2(bva, bva);
            u64 BQB = pk2(bqb, bqb), BKB = pk2(bkb, bkb), BVB = pk2(bvb, bvb);
            #pragma unroll
            for (int p = 0; p < 4; ++p) {
                int pg = pg0 + p, r0 = row0 + 2 * p, r1 = r0 + 1;
                float lo, hi;
                sts2(q2p + pg * 130 + tx * 2, add2(acc[p][0], BQA));
                sts2(q2p + pg * 130 + (32 + tx) * 2, add2(acc[p][3], BQB));
                upk2(add2(acc[p][1], BKA), lo, hi);
                k2[r0 * 65 + tx] = lo;        k2[r1 * 65 + tx] = hi;
                upk2(add2(acc[p][4], BKB), lo, hi);
                k2[r0 * 65 + 32 + tx] = lo;   k2[r1 * 65 + 32 + tx] = hi;
                upk2(add2(acc[p][2], BVA), lo, hi);
                v2[r0 * 65 + tx] = lo;        v2[r1 * 65 + tx] = hi;
                upk2(add2(acc[p][5], BVB), lo, hi);
                v2[r0 * 65 + 32 + tx] = lo;   v2[r1 * 65 + 32 + tx] = hi;
            }
        }
        __syncthreads();

        #pragma unroll
        for (int s = 0; s < 2; ++s) {
            const int hcol = (s == 0 ? hA : hB) * 32;
            const int kc0  = s * 32;
            // ---- GEMM2: scores, K=32 ----
            {
                u64 a2[4][2];
                #pragma unroll
                for (int p = 0; p < 4; ++p) { a2[p][0] = 0ULL; a2[p][1] = 0ULL; }
                #pragma unroll 4
                for (int kk = 0; kk < 32; ++kk) {
                    int kc = kc0 + kk;
                    float b0 = k2[tx * 65 + kc];
                    float b1 = k2[(tx + 32) * 65 + kc];
                    u64 B0 = pk2(b0, b0), B1 = pk2(b1, b1);
                    #pragma unroll
                    for (int p = 0; p < 4; ++p) {
                        u64 A = lds2(q2p + (pg0 + p) * 130 + kc * 2);
                        fma2(a2[p][0], A, B0); fma2(a2[p][1], A, B1);
                    }
                }
                #pragma unroll
                for (int p = 0; p < 4; ++p) {
                    sts2(scp + (pg0 + p) * 130 + tx * 2,        a2[p][0]);
                    sts2(scp + (pg0 + p) * 130 + (32 + tx) * 2, a2[p][1]);
                }
            }
            __syncwarp();
            // ---- softmax (warp-local rows) ----
            #pragma unroll
            for (int i = 0; i < 8; ++i) {
                int r = row0 + i;
                int sb = (r >> 1) * 130 + (r & 1);
                float s0 = scp[sb + tx * 2], s1 = scp[sb + (32 + tx) * 2];
                float mx = fmaxf(s0, s1);
                #pragma unroll
                for (int o = 16; o; o >>= 1) mx = fmaxf(mx, __shfl_xor_sync(0xffffffffu, mx, o));
                float e0 = __expf(s0 - mx), e1 = __expf(s1 - mx);
                float sum = e0 + e1;
                #pragma unroll
                for (int o = 16; o; o >>= 1) sum += __shfl_xor_sync(0xffffffffu, sum, o);
                float inv = 1.f / sum;
                scp[sb + tx * 2] = e0 * inv; scp[sb + (32 + tx) * 2] = e1 * inv;
            }
            __syncwarp();
            // ---- GEMM3: attn @ v, K=64 ----
            {
                u64 a3[4] = {0ULL, 0ULL, 0ULL, 0ULL};
                #pragma unroll 4
                for (int l = 0; l < 64; ++l) {
                    float bv = v2[l * 65 + kc0 + tx];
                    u64 B = pk2(bv, bv);
                    #pragma unroll
                    for (int p = 0; p < 4; ++p) {
                        u64 A = lds2(scp + (pg0 + p) * 130 + l * 2);
                        fma2(a3[p], A, B);
                    }
                }
                #pragma unroll
                for (int p = 0; p < 4; ++p)
                    sts2(obufp + (pg0 + p) * 512 + (hcol + tx) * 2, a3[p]);
            }
            __syncwarp();
        }
        __syncthreads();   // before next hp reuses q2p/k2/v2
    }

    // ---- out projection (smem-staged WoT tiles) + residual ----
    {
        u64 acc[4][8];
        #pragma unroll
        for (int p = 0; p < 4; ++p)
            #pragma unroll
            for (int j = 0; j < 8; ++j) acc[p][j] = 0ULL;

        float st[8];
        {
            const float* wg = g_WoT + w * 256;
            #pragma unroll
            for (int s2 = 0; s2 < 8; ++s2) st[s2] = wg[s2 * 32 + tx];
        }
        {
            float* wd = wbuf + w * 256;
            #pragma unroll
            for (int s2 = 0; s2 < 8; ++s2) wd[s2 * 32 + tx] = st[s2];
        }
        __syncthreads();

        const float* ap0 = obufp + (pg0 + 0) * 512;
        const float* ap1 = obufp + (pg0 + 1) * 512;
        const float* ap2 = obufp + (pg0 + 2) * 512;
        const float* ap3 = obufp + (pg0 + 3) * 512;

        for (int kt = 0; kt < 32; ++kt) {
            int cb = kt & 1, nb = cb ^ 1;
            if (kt < 31) {
                const float* wg = g_WoT + ((kt + 1) * 8 + w) * 256;
                #pragma unroll
                for (int s2 = 0; s2 < 8; ++s2) st[s2] = wg[s2 * 32 + tx];
            }
            const float* wt = wbuf + cb * 2048;
            #pragma unroll
            for (int kk = 0; kk < 8; ++kk) {
                const float* wr = wt + kk * 256;
                u64 W[8];
                #pragma unroll
                for (int j = 0; j < 8; ++j) { float wv = wr[j * 32 + tx]; W[j] = pk2(wv, wv); }
                const int kg2 = (kt * 8 + kk) * 2;
                u64 A0 = lds2(ap0 + kg2), A1 = lds2(ap1 + kg2);
                u64 A2 = lds2(ap2 + kg2), A3 = lds2(ap3 + kg2);
                #pragma unroll
                for (int j = 0; j < 8; ++j) fma2(acc[0][j], A0, W[j]);
                #pragma unroll
                for (int j = 0; j < 8; ++j) fma2(acc[1][j], A1, W[j]);
                #pragma unroll
                for (int j = 0; j < 8; ++j) fma2(acc[2][j], A2, W[j]);
                #pragma unroll
                for (int j = 0; j < 8; ++j) fma2(acc[3][j], A3, W[j]);
            }
            if (kt < 31) {
                float* wd = wbuf + nb * 2048 + w * 256;
                #pragma unroll
                for (int s2 = 0; s2 < 8; ++s2) wd[s2 * 32 + tx] = st[s2];
            }
            __syncthreads();
        }

        // residual: xn := xn*sd + mean + (o + b_out)   (pair ops)
        float bo[8];
        #pragma unroll
        for (int j = 0; j < 8; ++j) bo[j] = b_out[j * 32 + tx];
        #pragma unroll
        for (int p = 0; p < 4; ++p) {
            int pg = pg0 + p, r0 = row0 + 2 * p, r1 = r0 + 1;
            u64 S = pk2(sA[r0], sA[r1]);
            float m0 = mA[r0], m1 = mA[r1];
            #pragma unroll
            for (int j = 0; j < 8; ++j) {
                int c = j * 32 + tx;
                u64 t = acc[p][j];
                u64 X = lds2(xnp + pg * 512 + c * 2);
                fma2(t, X, S);                      // t = X*sd + o
                t = add2(t, pk2(m0 + bo[j], m1 + bo[j]));
                sts2(xnp + pg * 512 + c * 2, t);
            }
        }
    }
    __syncwarp();

    // ---- final LN + store ----
    for (int i = 0; i < 8; ++i) {
        int r = row0 + i;
        int base = (r >> 1) * 512 + (r & 1);
        float s = 0.f, ss = 0.f;
        #pragma unroll
        for (int c = tx; c < 256; c += 32) { float v = xnp[base + c * 2]; s += v; ss += v * v; }
        #pragma unroll
        for (int o = 16; o; o >>= 1) { s  += __shfl_xor_sync(0xffffffffu, s,  o);
                                       ss += __shfl_xor_sync(0xffffffffu, ss, o); }
        float mean = s * (1.f / 256.f);
        float var  = ss * (1.f / 256.f) - mean * mean;
        float inv  = rsqrtf(var + EPS);
        int off = gbase + (r >> 3) * (64 * 256) + (r & 7) * 256;
        #pragma unroll
        for (int c = tx; c < 256; c += 32) {
            float v = (xnp[base + c * 2] - mean) * inv;
            y[off + c] = v * g_o[c] + b_o[c];
        }
    }
}

static const int SMEM_BYTES = 53632 * (int)sizeof(float);   // 214528 B

extern "C" void kernel_launch(void* const* d_in, const int* in_sizes, int n_in,
                              void* d_out, int out_size) {
    (void)in_sizes; (void)n_in; (void)out_size;
    const float* x     = (const float*)d_in[0];
    const float* w_in  = (const float*)d_in[1];
    const float* b_in  = (const float*)d_in[2];
    const float* w_out = (const float*)d_in[3];
    const float* b_out = (const float*)d_in[4];
    const float* g_q   = (const float*)d_in[5];
    const float* b_q   = (const float*)d_in[6];
    const float* g_k   = (const float*)d_in[7];
    const float* b_k   = (const float*)d_in[8];
    const float* g_v   = (const float*)d_in[9];
    const float* b_v   = (const float*)d_in[10];
    const float* g_o   = (const float*)d_in[11];
    const float* b_o   = (const float*)d_in[12];
    float* y = (float*)d_out;

    cudaFuncSetAttribute(win_attn_kernel, cudaFuncAttributeMaxDynamicSharedMemorySize, SMEM_BYTES);

    prep_w_kernel<<<768, 256>>>(w_in, b_in, g_q, b_q, g_k, b_k, g_v, b_v);
    prep_wo_kernel<<<256, 256>>>(w_out);
    win_attn_kernel<<<2048, 256, SMEM_BYTES>>>(x, b_out, g_o, b_o, y);
}

// round 9
// speedup vs baseline: 1.0012x; 1.0012x over previous
#include <cuda_runtime.h>
#include <math.h>

// WindowAttention: B=32, 64x64, C=256, ws=8 -> 2048 windows of 64 tokens.
// One CTA (256 threads) per window. fp32 FFMA2 with:
//  - pair-interleaved A-side smem layouts (LDS.64 operands, STS.64 epilogues)
//  - double-buffered smem weight tiles (kills hot-loop LDG pressure)
//  - q-scale folded into prepped weights.

#define EPS 1e-5f

__device__ float g_Wt[256 * 768];    // Wt[k][col] = w_in[col][k] * g_branch[k] (*invsqd for q cols)
__device__ float g_bias[768];
__device__ float g_WoT[256 * 256];   // WoT[k][j] = w_out[j][k]

typedef unsigned long long u64;

__device__ __forceinline__ u64 pk2(float lo, float hi) {
    u64 r; asm("mov.b64 %0, {%1, %2};" : "=l"(r) : "f"(lo), "f"(hi)); return r;
}
__device__ __forceinline__ void upk2(u64 v, float& lo, float& hi) {
    asm("mov.b64 {%0, %1}, %2;" : "=f"(lo), "=f"(hi) : "l"(v));
}
__device__ __forceinline__ void fma2(u64& d, u64 a, u64 b) {
    asm("fma.rn.f32x2 %0, %1, %2, %3;" : "=l"(d) : "l"(a), "l"(b), "l"(d));
}
__device__ __forceinline__ u64 add2(u64 a, u64 b) {
    u64 r; asm("add.rn.f32x2 %0, %1, %2;" : "=l"(r) : "l"(a), "l"(b)); return r;
}
__device__ __forceinline__ u64 lds2(const float* p) {
    return *reinterpret_cast<const u64*>(p);
}
__device__ __forceinline__ void sts2(float* p, u64 v) {
    *reinterpret_cast<u64*>(p) = v;
}

// ---- prep: fold LN affine (and q-scale) into packed in_proj, k-major ----
__global__ void prep_w_kernel(const float* __restrict__ w_in, const float* __restrict__ b_in,
                              const float* __restrict__ g_q, const float* __restrict__ b_q,
                              const float* __restrict__ g_k, const float* __restrict__ b_k,
                              const float* __restrict__ g_v, const float* __restrict__ b_v) {
    __shared__ float red[8];
    int col = blockIdx.x;       // 0..767
    int k   = threadIdx.x;      // 0..255
    const float* g; const float* b;
    if (col < 256)      { g = g_q; b = b_q; }
    else if (col < 512) { g = g_k; b = b_k; }
    else                { g = g_v; b = b_v; }
    const float f = (col < 256) ? 0.17677669529663689f : 1.0f;   // 1/sqrt(32) folded into q
    float w = w_in[col * 256 + k];
    g_Wt[k * 768 + col] = w * g[k] * f;
    float p = w * b[k];
    #pragma unroll
    for (int o = 16; o; o >>= 1) p += __shfl_xor_sync(0xffffffffu, p, o);
    if ((k & 31) == 0) red[k >> 5] = p;
    __syncthreads();
    if (k < 8) {
        float s = red[k];
        #pragma unroll
        for (int o = 4; o; o >>= 1) s += __shfl_xor_sync(0xffu, s, o);
        if (k == 0) g_bias[col] = (b_in[col] + s) * f;
    }
}

__global__ void prep_wo_kernel(const float* __restrict__ w_out) {
    int idx = blockIdx.x * 256 + threadIdx.x;   // 65536 elements
    int j = idx >> 8, k = idx & 255;
    g_WoT[k * 256 + j] = w_out[idx];
}

// ---- main fused window-attention kernel ----
// smem (floats):
//  xnp   [32][256][2]  pair-interleaved normalized input / residual   16384
//  obufp [32][256][2]  pair-interleaved attention output              16384
//  q2p   [32][65*2]    pair-interleaved q (2 heads, 64 cols, pad)      4160
//  k2    [64][65]      row-major k                                     4160
//  v2    [64][65]      row-major v                                     4160
//  scp   [32][65*2]    pair-interleaved scores                         4160
//  wbuf  double-buffered weight tiles (GEMM1: 2x1536, outproj: 2x2048) 4096
//  mA,sA [64] each                                                      128
__global__ __launch_bounds__(256, 1)
void win_attn_kernel(const float* __restrict__ x, const float* __restrict__ b_out,
                     const float* __restrict__ g_o, const float* __restrict__ b_o,
                     float* __restrict__ y) {
    extern __shared__ float sm[];
    float* xnp   = sm;             // 16384
    float* obufp = sm + 16384;     // 16384
    float* q2p   = sm + 32768;     // 4160
    float* k2    = sm + 36928;     // 4160
    float* v2    = sm + 41088;     // 4160
    float* scp   = sm + 45248;     // 4160
    float* wbuf  = sm + 49408;     // 4096
    float* mA    = sm + 53504;     // 64
    float* sA    = sm + 53568;     // 64   total 53632 floats = 214528 B

    const int tid  = threadIdx.x;
    const int w    = tid >> 5;
    const int tx   = tid & 31;
    const int row0 = w * 8;
    const int pg0  = w * 4;        // warp owns row-pairs pg0..pg0+3

    const int win = blockIdx.x;
    const int b   = win >> 6;
    const int wh  = (win >> 3) & 7;
    const int ww  = win & 7;
    const int gbase = ((b * 64 + wh * 8) * 64 + ww * 8) * 256;

    // ---- load window into pair-interleaved smem ----
    for (int t = 0; t < 64; ++t) {
        int off = gbase + (t >> 3) * (64 * 256) + (t & 7) * 256;
        xnp[(t >> 1) * 512 + tid * 2 + (t & 1)] = x[off + tid];
    }
    __syncthreads();

    // ---- LN stats + normalize in place (warp-local rows) ----
    for (int i = 0; i < 8; ++i) {
        int r = row0 + i;
        int base = (r >> 1) * 512 + (r & 1);
        float s = 0.f, ss = 0.f;
        #pragma unroll
        for (int c = tx; c < 256; c += 32) { float v = xnp[base + c * 2]; s += v; ss += v * v; }
        #pragma unroll
        for (int o = 16; o; o >>= 1) { s  += __shfl_xor_sync(0xffffffffu, s,  o);
                                       ss += __shfl_xor_sync(0xffffffffu, ss, o); }
        float mean = s * (1.f / 256.f);
        float var  = ss * (1.f / 256.f) - mean * mean;
        float sd   = sqrtf(var + EPS);
        float inv  = 1.f / sd;
        if (tx == 0) { mA[r] = mean; sA[r] = sd; }
        #pragma unroll
        for (int c = tx; c < 256; c += 32) xnp[base + c * 2] = (xnp[base + c * 2] - mean) * inv;
    }
    __syncthreads();

    for (int hp = 0; hp < 4; ++hp) {
        const int hA = hp, hB = hp + 4;
        const int cA = hA * 32 + tx, cB = hB * 32 + tx;

        // ---- GEMM1: q,k,v for heads hA,hB; weights staged in smem ----
        {
            u64 acc[4][6];
            #pragma unroll
            for (int p = 0; p < 4; ++p)
                #pragma unroll
                for (int j = 0; j < 6; ++j) acc[p][j] = 0ULL;

            // preload tile 0 (warp w stages kk row w of the tile; 6 segments)
            float st0, st1, st2, st3, st4, st5;
            {
                const float* wg = g_Wt + w * 768;
                st0 = wg[cA]; st1 = wg[256 + cA]; st2 = wg[512 + cA];
                st3 = wg[cB]; st4 = wg[256 + cB]; st5 = wg[512 + cB];
            }
            {
                float* wd = wbuf + w * 192;
                wd[tx] = st0; wd[32 + tx] = st1; wd[64 + tx] = st2;
                wd[96 + tx] = st3; wd[128 + tx] = st4; wd[160 + tx] = st5;
            }
            __syncthreads();

            const float* ap0 = xnp + (pg0 + 0) * 512;
            const float* ap1 = xnp + (pg0 + 1) * 512;
            const float* ap2 = xnp + (pg0 + 2) * 512;
            const float* ap3 = xnp + (pg0 + 3) * 512;

            for (int kt = 0; kt < 32; ++kt) {
                int cb = kt & 1, nb = cb ^ 1;
                if (kt < 31) {
                    const float* wg = g_Wt + ((kt + 1) * 8 + w) * 768;
                    st0 = wg[cA]; st1 = wg[256 + cA]; st2 = wg[512 + cA];
                    st3 = wg[cB]; st4 = wg[256 + cB]; st5 = wg[512 + cB];
                }
                const float* wt = wbuf + cb * 1536;
                #pragma unroll
                for (int kk = 0; kk < 8; ++kk) {
                    const float* wr = wt + kk * 192;
                    float w0 = wr[tx],      w1 = wr[32 + tx],  w2 = wr[64 + tx];
                    float w3 = wr[96 + tx], w4 = wr[128 + tx], w5 = wr[160 + tx];
                    u64 W0 = pk2(w0, w0), W1 = pk2(w1, w1), W2 = pk2(w2, w2);
                    u64 W3 = pk2(w3, w3), W4 = pk2(w4, w4), W5 = pk2(w5, w5);
                    const int kg2 = (kt * 8 + kk) * 2;
                    u64 A0 = lds2(ap0 + kg2), A1 = lds2(ap1 + kg2);
                    u64 A2 = lds2(ap2 + kg2), A3 = lds2(ap3 + kg2);
                    fma2(acc[0][0], A0, W0); fma2(acc[0][1], A0, W1); fma2(acc[0][2], A0, W2);
                    fma2(acc[0][3], A0, W3); fma2(acc[0][4], A0, W4); fma2(acc[0][5], A0, W5);
                    fma2(acc[1][0], A1, W0); fma2(acc[1][1], A1, W1); fma2(acc[1][2], A1, W2);
                    fma2(acc[1][3], A1, W3); fma2(acc[1][4], A1, W4); fma2(acc[1][5], A1, W5);
                    fma2(acc[2][0], A2, W0); fma2(acc[2][1], A2, W1); fma2(acc[2][2], A2, W2);
                    fma2(acc[2][3], A2, W3); fma2(acc[2][4], A2, W4); fma2(acc[2][5], A2, W5);
                    fma2(acc[3][0], A3, W0); fma2(acc[3][1], A3, W1); fma2(acc[3][2], A3, W2);
                    fma2(acc[3][3], A3, W3); fma2(acc[3][4], A3, W4); fma2(acc[3][5], A3, W5);
                }
                if (kt < 31) {
                    float* wd = wbuf + nb * 1536 + w * 192;
                    wd[tx] = st0; wd[32 + tx] = st1; wd[64 + tx] = st2;
                    wd[96 + tx] = st3; wd[128 + tx] = st4; wd[160 + tx] = st5;
                }
                __syncthreads();
            }

            // epilogue: add bias, store q (pairs), k/v (row-major)
            float bqa = g_bias[cA], bka = g_bias[256 + cA], bva = g_bias[512 + cA];
            float bqb = g_bias[cB], bkb = g_bias[256 + cB], bvb = g_bias[512 + cB];
            u64 BQA = pk2(bqa, bqa), BKA = pk2(bka, bka), BVA = pk2(bva, bva);
            u64 BQB = pk2(bqb, bqb), BKB = pk2(bkb, bkb), BVB = pk2(bvb, bvb);
            #pragma unroll
            for (int p = 0; p < 4; ++p) {
                int pg = pg0 + p, r0 = row0 + 2 * p, r1 = r0 + 1;
                float lo, hi;
                sts2(q2p + pg * 130 + tx * 2, add2(acc[p][0], BQA));
                sts2(q2p + pg * 130 + (32 + tx) * 2, add2(acc[p][3], BQB));
                upk2(add2(acc[p][1], BKA), lo, hi);
                k2[r0 * 65 + tx] = lo;        k2[r1 * 65 + tx] = hi;
                upk2(add2(acc[p][4], BKB), lo, hi);
                k2[r0 * 65 + 32 + tx] = lo;   k2[r1 * 65 + 32 + tx] = hi;
                upk2(add2(acc[p][2], BVA), lo, hi);
                v2[r0 * 65 + tx] = lo;        v2[r1 * 65 + tx] = hi;
                upk2(add2(acc[p][5], BVB), lo, hi);
                v2[r0 * 65 + 32 + tx] = lo;   v2[r1 * 65 + 32 + tx] = hi;
            }
        }
        __syncthreads();

        #pragma unroll
        for (int s = 0; s < 2; ++s) {
            const int hcol = (s == 0 ? hA : hB) * 32;
            const int kc0  = s * 32;
            // ---- GEMM2: scores, K=32 ----
            {
                u64 a2[4][2];
                #pragma unroll
                for (int p = 0; p < 4; ++p) { a2[p][0] = 0ULL; a2[p][1] = 0ULL; }
                #pragma unroll 4
                for (int kk = 0; kk < 32; ++kk) {
                    int kc = kc0 + kk;
                    float b0 = k2[tx * 65 + kc];
                    float b1 = k2[(tx + 32) * 65 + kc];
                    u64 B0 = pk2(b0, b0), B1 = pk2(b1, b1);
                    #pragma unroll
                    for (int p = 0; p < 4; ++p) {
                        u64 A = lds2(q2p + (pg0 + p) * 130 + kc * 2);
                        fma2(a2[p][0], A, B0); fma2(a2[p][1], A, B1);
                    }
                }
                #pragma unroll
                for (int p = 0; p < 4; ++p) {
                    sts2(scp + (pg0 + p) * 130 + tx * 2,        a2[p][0]);
                    sts2(scp + (pg0 + p) * 130 + (32 + tx) * 2, a2[p][1]);
                }
            }
            __syncwarp();
            // ---- softmax (warp-local rows) ----
            #pragma unroll
            for (int i = 0; i < 8; ++i) {
                int r = row0 + i;
                int sb = (r >> 1) * 130 + (r & 1);
                float s0 = scp[sb + tx * 2], s1 = scp[sb + (32 + tx) * 2];
                float mx = fmaxf(s0, s1);
                #pragma unroll
                for (int o = 16; o; o >>= 1) mx = fmaxf(mx, __shfl_xor_sync(0xffffffffu, mx, o));
                float e0 = __expf(s0 - mx), e1 = __expf(s1 - mx);
                float sum = e0 + e1;
                #pragma unroll
                for (int o = 16; o; o >>= 1) sum += __shfl_xor_sync(0xffffffffu, sum, o);
                float inv = 1.f / sum;
                scp[sb + tx * 2] = e0 * inv; scp[sb + (32 + tx) * 2] = e1 * inv;
            }
            __syncwarp();
            // ---- GEMM3: attn @ v, K=64 ----
            {
                u64 a3[4] = {0ULL, 0ULL, 0ULL, 0ULL};
                #pragma unroll 4
                for (int l = 0; l < 64; ++l) {
                    float bv = v2[l * 65 + kc0 + tx];
                    u64 B = pk2(bv, bv);
                    #pragma unroll
                    for (int p = 0; p < 4; ++p) {
                        u64 A = lds2(scp + (pg0 + p) * 130 + l * 2);
                        fma2(a3[p], A, B);
                    }
                }
                #pragma unroll
                for (int p = 0; p < 4; ++p)
                    sts2(obufp + (pg0 + p) * 512 + (hcol + tx) * 2, a3[p]);
            }
            __syncwarp();
        }
        __syncthreads();   // before next hp reuses q2p/k2/v2
    }

    // ---- out projection (smem-staged WoT tiles) + residual ----
    {
        u64 acc[4][8];
        #pragma unroll
        for (int p = 0; p < 4; ++p)
            #pragma unroll
            for (int j = 0; j < 8; ++j) acc[p][j] = 0ULL;

        float st[8];
        {
            const float* wg = g_WoT + w * 256;
            #pragma unroll
            for (int s2 = 0; s2 < 8; ++s2) st[s2] = wg[s2 * 32 + tx];
        }
        {
            float* wd = wbuf + w * 256;
            #pragma unroll
            for (int s2 = 0; s2 < 8; ++s2) wd[s2 * 32 + tx] = st[s2];
        }
        __syncthreads();

        const float* ap0 = obufp + (pg0 + 0) * 512;
        const float* ap1 = obufp + (pg0 + 1) * 512;
        const float* ap2 = obufp + (pg0 + 2) * 512;
        const float* ap3 = obufp + (pg0 + 3) * 512;

        for (int kt = 0; kt < 32; ++kt) {
            int cb = kt & 1, nb = cb ^ 1;
            if (kt < 31) {
                const float* wg = g_WoT + ((kt + 1) * 8 + w) * 256;
                #pragma unroll
                for (int s2 = 0; s2 < 8; ++s2) st[s2] = wg[s2 * 32 + tx];
            }
            const float* wt = wbuf + cb * 2048;
            #pragma unroll
            for (int kk = 0; kk < 8; ++kk) {
                const float* wr = wt + kk * 256;
                u64 W[8];
                #pragma unroll
                for (int j = 0; j < 8; ++j) { float wv = wr[j * 32 + tx]; W[j] = pk2(wv, wv); }
                const int kg2 = (kt * 8 + kk) * 2;
                u64 A0 = lds2(ap0 + kg2), A1 = lds2(ap1 + kg2);
                u64 A2 = lds2(ap2 + kg2), A3 = lds2(ap3 + kg2);
                #pragma unroll
                for (int j = 0; j < 8; ++j) fma2(acc[0][j], A0, W[j]);
                #pragma unroll
                for (int j = 0; j < 8; ++j) fma2(acc[1][j], A1, W[j]);
                #pragma unroll
                for (int j = 0; j < 8; ++j) fma2(acc[2][j], A2, W[j]);
                #pragma unroll
                for (int j = 0; j < 8; ++j) fma2(acc[3][j], A3, W[j]);
            }
            if (kt < 31) {
                float* wd = wbuf + nb * 2048 + w * 256;
                #pragma unroll
                for (int s2 = 0; s2 < 8; ++s2) wd[s2 * 32 + tx] = st[s2];
            }
            __syncthreads();
        }

        // residual: xn := xn*sd + mean + (o + b_out)   (pair ops)
        float bo[8];
        #pragma unroll
        for (int j = 0; j < 8; ++j) bo[j] = b_out[j * 32 + tx];
        #pragma unroll
        for (int p = 0; p < 4; ++p) {
            int pg = pg0 + p, r0 = row0 + 2 * p, r1 = r0 + 1;
            u64 S = pk2(sA[r0], sA[r1]);
            float m0 = mA[r0], m1 = mA[r1];
            #pragma unroll
            for (int j = 0; j < 8; ++j) {
                int c = j * 32 + tx;
                u64 t = acc[p][j];
                u64 X = lds2(xnp + pg * 512 + c * 2);
                fma2(t, X, S);                      // t = X*sd + o
                t = add2(t, pk2(m0 + bo[j], m1 + bo[j]));
                sts2(xnp + pg * 512 + c * 2, t);
            }
        }
    }
    __syncwarp();

    // ---- final LN + store ----
    for (int i = 0; i < 8; ++i) {
        int r = row0 + i;
        int base = (r >> 1) * 512 + (r & 1);
        float s = 0.f, ss = 0.f;
        #pragma unroll
        for (int c = tx; c < 256; c += 32) { float v = xnp[base + c * 2]; s += v; ss += v * v; }
        #pragma unroll
        for (int o = 16; o; o >>= 1) { s  += __shfl_xor_sync(0xffffffffu, s,  o);
                                       ss += __shfl_xor_sync(0xffffffffu, ss, o); }
        float mean = s * (1.f / 256.f);
        float var  = ss * (1.f / 256.f) - mean * mean;
        float inv  = rsqrtf(var + EPS);
        int off = gbase + (r >> 3) * (64 * 256) + (r & 7) * 256;
        #pragma unroll
        for (int c = tx; c < 256; c += 32) {
            float v = (xnp[base + c * 2] - mean) * inv;
            y[off + c] = v * g_o[c] + b_o[c];
        }
    }
}

static const int SMEM_BYTES = 53632 * (int)sizeof(float);   // 214528 B

extern "C" void kernel_launch(void* const* d_in, const int* in_sizes, int n_in,
                              void* d_out, int out_size) {
    (void)in_sizes; (void)n_in; (void)out_size;
    const float* x     = (const float*)d_in[0];
    const float* w_in  = (const float*)d_in[1];
    const float* b_in  = (const float*)d_in[2];
    const float* w_out = (const float*)d_in[3];
    const float* b_out = (const float*)d_in[4];
    const float* g_q   = (const float*)d_in[5];
    const float* b_q   = (const float*)d_in[6];
    const float* g_k   = (const float*)d_in[7];
    const float* b_k   = (const float*)d_in[8];
    const float* g_v   = (const float*)d_in[9];
    const float* b_v   = (const float*)d_in[10];
    const float* g_o   = (const float*)d_in[11];
    const float* b_o   = (const float*)d_in[12];
    float* y = (float*)d_out;

    cudaFuncSetAttribute(win_attn_kernel, cudaFuncAttributeMaxDynamicSharedMemorySize, SMEM_BYTES);

    prep_w_kernel<<<768, 256>>>(w_in, b_in, g_q, b_q, g_k, b_k, g_v, b_v);
    prep_wo_kernel<<<256, 256>>>(w_out);
    win_attn_kernel<<<2048, 256, SMEM_BYTES>>>(x, b_out, g_o, b_o, y);
}

// round 11
// speedup vs baseline: 1.7939x; 1.7917x over previous
#include <cuda_runtime.h>
#include <cuda_bf16.h>
#include <math.h>
#include <stdint.h>

// WindowAttention via mma.sync (HMMA) bf16 hi/lo-split GEMMs + fp32 attention.
// B=32, 64x64, C=256, ws=8 -> MT=131072 token rows. No tcgen05 (harness
// compiles at compute_103 without the 'a' feature).

#define EPS 1e-5f
#define MT 131072

// scratch pool (aliased):
//  [0, 384MB)     qkv fp32 [MT][768]   ; later z fp32 [MT][256]
//  [384MB,448MB)  xh bf16 [MT][256]    ; later oh
//  [448MB,512MB)  xl bf16 [MT][256]    ; later ol
__device__ __align__(256) unsigned char g_pool[536870912ULL];

__device__ __nv_bfloat16 g_wh[768 * 256];
__device__ __nv_bfloat16 g_wl[768 * 256];
__device__ float         g_bias[768];
__device__ __nv_bfloat16 g_woh[256 * 256];
__device__ __nv_bfloat16 g_wol[256 * 256];

typedef unsigned long long u64;
typedef unsigned int u32;

__device__ __forceinline__ u64 pk2(float lo, float hi) {
    u64 r; asm("mov.b64 %0, {%1, %2};" : "=l"(r) : "f"(lo), "f"(hi)); return r;
}
__device__ __forceinline__ void upk2(u64 v, float& lo, float& hi) {
    asm("mov.b64 {%0, %1}, %2;" : "=f"(lo), "=f"(hi) : "l"(v));
}
__device__ __forceinline__ void fma2(u64& d, u64 a, u64 b) {
    asm("fma.rn.f32x2 %0, %1, %2, %3;" : "=l"(d) : "l"(a), "l"(b), "l"(d));
}
__device__ __forceinline__ u64 lds2(const float* p) { return *reinterpret_cast<const u64*>(p); }

__device__ __forceinline__ uint32_t smem_u32(const void* p) {
    uint32_t a;
    asm("{ .reg .u64 t; cvta.to.shared.u64 t, %1; cvt.u32.u64 %0, t; }" : "=r"(a) : "l"(p));
    return a;
}
__device__ __forceinline__ void cpa16(void* dst, const void* src) {
    asm volatile("cp.async.cg.shared.global [%0], [%1], 16;"
                 :: "r"(smem_u32(dst)), "l"(src) : "memory");
}
#define CP_COMMIT() asm volatile("cp.async.commit_group;" ::: "memory")
#define CP_WAIT(n)  asm volatile("cp.async.wait_group %0;" :: "n"(n) : "memory")

#define MMA16816(d, a, b) \
    asm volatile("mma.sync.aligned.m16n8k16.row.col.f32.bf16.bf16.f32 " \
        "{%0,%1,%2,%3}, {%4,%5,%6,%7}, {%8,%9}, {%0,%1,%2,%3};" \
        : "+f"((d)[0]), "+f"((d)[1]), "+f"((d)[2]), "+f"((d)[3]) \
        : "r"((a)[0]), "r"((a)[1]), "r"((a)[2]), "r"((a)[3]), \
          "r"((b)[0]), "r"((b)[1]))

__device__ __forceinline__ int row_goff(int r) {
    int win = r >> 6, t = r & 63;
    int b = win >> 6, wh8 = (win >> 3) & 7, ww = win & 7;
    return ((b * 64 + wh8 * 8 + (t >> 3)) * 64 + ww * 8 + (t & 7)) * 256;
}

// ---- prep: fold LN affine (+q scale) into in_proj, split hi/lo bf16 ----
__global__ void prep_w_kernel(const float* __restrict__ w_in, const float* __restrict__ b_in,
                              const float* __restrict__ g_q, const float* __restrict__ b_q,
                              const float* __restrict__ g_k, const float* __restrict__ b_k,
                              const float* __restrict__ g_v, const float* __restrict__ b_v) {
    __shared__ float red[8];
    int col = blockIdx.x, k = threadIdx.x;
    const float* g; const float* b;
    if (col < 256)      { g = g_q; b = b_q; }
    else if (col < 512) { g = g_k; b = b_k; }
    else                { g = g_v; b = b_v; }
    const float f = (col < 256) ? 0.17677669529663689f : 1.0f;   // 1/sqrt(32)
    float w  = w_in[col * 256 + k];
    float wf = w * g[k] * f;
    __nv_bfloat16 hi = __float2bfloat16(wf);
    g_wh[col * 256 + k] = hi;
    g_wl[col * 256 + k] = __float2bfloat16(wf - __bfloat162float(hi));
    float p = w * b[k];
    #pragma unroll
    for (int o = 16; o; o >>= 1) p += __shfl_xor_sync(0xffffffffu, p, o);
    if ((k & 31) == 0) red[k >> 5] = p;
    __syncthreads();
    if (k < 8) {
        float s = red[k];
        #pragma unroll
        for (int o = 4; o; o >>= 1) s += __shfl_xor_sync(0xffu, s, o);
        if (k == 0) g_bias[col] = (b_in[col] + s) * f;
    }
}

__global__ void prep_wo_kernel(const float* __restrict__ w_out) {
    int idx = blockIdx.x * 256 + threadIdx.x;
    float v = w_out[idx];
    __nv_bfloat16 hi = __float2bfloat16(v);
    g_woh[idx] = hi;
    g_wol[idx] = __float2bfloat16(v - __bfloat162float(hi));
}

// ---- LN + hi/lo split ----
__global__ __launch_bounds__(256)
void ln_split_kernel(const float* __restrict__ x) {
    __nv_bfloat16* xh = (__nv_bfloat16*)(g_pool + 402653184ULL);
    __nv_bfloat16* xl = (__nv_bfloat16*)(g_pool + 469762048ULL);
    int w = threadIdx.x >> 5, tx = threadIdx.x & 31;
    int r = blockIdx.x * 8 + w;
    int goff = row_goff(r);
    float v[8], s = 0.f, ss = 0.f;
    #pragma unroll
    for (int i = 0; i < 8; ++i) { v[i] = x[goff + tx + 32 * i]; s += v[i]; ss += v[i] * v[i]; }
    #pragma unroll
    for (int o = 16; o; o >>= 1) { s  += __shfl_xor_sync(0xffffffffu, s,  o);
                                   ss += __shfl_xor_sync(0xffffffffu, ss, o); }
    float mean = s * (1.f / 256.f);
    float inv  = rsqrtf(ss * (1.f / 256.f) - mean * mean + EPS);
    #pragma unroll
    for (int i = 0; i < 8; ++i) {
        float xn = (v[i] - mean) * inv;
        __nv_bfloat16 hi = __float2bfloat16(xn);
        size_t dst = (size_t)r * 256 + tx + 32 * i;
        xh[dst] = hi;
        xl[dst] = __float2bfloat16(xn - __bfloat162float(hi));
    }
}

// ---- HMMA bf16-split GEMM: phase0 qkv = xn@Win^T+bias; phase1 z = o@Wout^T ----
// CTA 128x128 tile, 8 warps (2x4), warp tile 64x32. K=256 in 8 chunks of 32,
// cp.async double-buffered. smem row stride 40 halves (conflict-free frags).
static const int CHUNK_H = 128 * 40;             // halves per array per buffer
static const int SMEM_GEMM = 2 * 4 * CHUNK_H * 2; // 81920 B

__global__ __launch_bounds__(256, 1)
void gemm_split_kernel(int phase) {
    extern __shared__ __nv_bfloat16 smh[];
    const int tid = threadIdx.x, wid = tid >> 5, lane = tid & 31;
    const int gid = lane >> 2, tig = lane & 3;
    const int mw = wid >> 2, nw = wid & 3;       // warp grid 2x4
    const int mt = blockIdx.x, nt = blockIdx.y;

    const __nv_bfloat16* Asrc_h = (const __nv_bfloat16*)(g_pool + 402653184ULL);
    const __nv_bfloat16* Asrc_l = (const __nv_bfloat16*)(g_pool + 469762048ULL);
    const __nv_bfloat16* Bsrc_h = phase ? g_woh : g_wh;
    const __nv_bfloat16* Bsrc_l = phase ? g_wol : g_wl;
    float* out = (float*)g_pool;
    const int oc = phase ? 256 : 768;

    // per-thread prefetch mapping: 2048 16B copies / 256 threads = 8 each
    // idx = tid + t*256 ; arr = idx>>9 (0:Ah 1:Al 2:Bh 3:Bl) ; e = idx&511 ;
    // row = e>>2 ; seg = e&3
    const __nv_bfloat16* srcs[4] = {
        Asrc_h + (size_t)(mt * 128) * 256,
        Asrc_l + (size_t)(mt * 128) * 256,
        Bsrc_h + (size_t)(nt * 128) * 256,
        Bsrc_l + (size_t)(nt * 128) * 256 };

    auto prefetch = [&](int kc, int buf) {
        __nv_bfloat16* base = smh + buf * (4 * CHUNK_H);
        #pragma unroll
        for (int t = 0; t < 8; ++t) {
            int idx = tid + t * 256;
            int arr = idx >> 9, e = idx & 511, row = e >> 2, seg = e & 3;
            cpa16(base + arr * CHUNK_H + row * 40 + seg * 8,
                  srcs[arr] + (size_t)row * 256 + kc * 32 + seg * 8);
        }
    };

    float acc[4][4][4];
    #pragma unroll
    for (int m = 0; m < 4; ++m)
        #pragma unroll
        for (int n = 0; n < 4; ++n)
            #pragma unroll
            for (int q = 0; q < 4; ++q) acc[m][n][q] = 0.f;

    prefetch(0, 0);
    CP_COMMIT();

    for (int kc = 0; kc < 8; ++kc) {
        if (kc + 1 < 8) prefetch(kc + 1, (kc + 1) & 1);
        CP_COMMIT();
        CP_WAIT(1);
        __syncthreads();
        const __nv_bfloat16* bAh = smh + (kc & 1) * (4 * CHUNK_H);
        const __nv_bfloat16* bAl = bAh + CHUNK_H;
        const __nv_bfloat16* bBh = bAh + 2 * CHUNK_H;
        const __nv_bfloat16* bBl = bAh + 3 * CHUNK_H;
        #pragma unroll
        for (int ks = 0; ks < 2; ++ks) {
            const int ko = ks * 16 + tig * 2;
            u32 ah[4][4], al[4][4], bh[4][2], bl[4][2];
            #pragma unroll
            for (int m = 0; m < 4; ++m) {
                const __nv_bfloat16* p = bAh + (mw * 64 + m * 16 + gid) * 40 + ko;
                ah[m][0] = *(const u32*)p;           ah[m][1] = *(const u32*)(p + 8 * 40);
                ah[m][2] = *(const u32*)(p + 8);     ah[m][3] = *(const u32*)(p + 8 * 40 + 8);
                const __nv_bfloat16* q = bAl + (mw * 64 + m * 16 + gid) * 40 + ko;
                al[m][0] = *(const u32*)q;           al[m][1] = *(const u32*)(q + 8 * 40);
                al[m][2] = *(const u32*)(q + 8);     al[m][3] = *(const u32*)(q + 8 * 40 + 8);
            }
            #pragma unroll
            for (int n = 0; n < 4; ++n) {
                const __nv_bfloat16* p = bBh + (nw * 32 + n * 8 + gid) * 40 + ko;
                bh[n][0] = *(const u32*)p;           bh[n][1] = *(const u32*)(p + 8);
                const __nv_bfloat16* q = bBl + (nw * 32 + n * 8 + gid) * 40 + ko;
                bl[n][0] = *(const u32*)q;           bl[n][1] = *(const u32*)(q + 8);
            }
            #pragma unroll
            for (int m = 0; m < 4; ++m)
                #pragma unroll
                for (int n = 0; n < 4; ++n) {
                    MMA16816(acc[m][n], ah[m], bh[n]);   // hh
                    MMA16816(acc[m][n], ah[m], bl[n]);   // hl
                    MMA16816(acc[m][n], al[m], bh[n]);   // lh
                }
        }
        __syncthreads();
    }

    // epilogue: direct global stores (8B pairs), + bias for phase0
    const bool has_bias = (phase == 0);
    #pragma unroll
    for (int m = 0; m < 4; ++m) {
        int row = mt * 128 + mw * 64 + m * 16 + gid;
        #pragma unroll
        for (int n = 0; n < 4; ++n) {
            int col = nt * 128 + nw * 32 + n * 8 + tig * 2;
            float b0 = 0.f, b1 = 0.f;
            if (has_bias) { b0 = g_bias[col]; b1 = g_bias[col + 1]; }
            float2 v0 = make_float2(acc[m][n][0] + b0, acc[m][n][1] + b1);
            float2 v1 = make_float2(acc[m][n][2] + b0, acc[m][n][3] + b1);
            *(float2*)(out + (size_t)row * oc + col)       = v0;
            *(float2*)(out + (size_t)(row + 8) * oc + col) = v1;
        }
    }
}

// ---- attention: CTA = win*8 + head, 64 threads, fp32 FFMA2 ----
__global__ __launch_bounds__(64)
void attn_kernel() {
    __shared__ float qs[64 * 34], ks_[64 * 34], vs[64 * 34], ssm[64 * 65];
    const float* qkv = (const float*)g_pool;
    __nv_bfloat16* oh = (__nv_bfloat16*)(g_pool + 402653184ULL);
    __nv_bfloat16* ol = (__nv_bfloat16*)(g_pool + 469762048ULL);

    int t = threadIdx.x;
    int win = blockIdx.x >> 3, h = blockIdx.x & 7;
    int R = win * 64;
    {
        int c = t & 31, r0 = t >> 5;
        for (int i = 0; i < 32; ++i) {
            int r = r0 + 2 * i;
            size_t base = (size_t)(R + r) * 768 + h * 32 + c;
            qs[r * 34 + c]  = qkv[base];
            ks_[r * 34 + c] = qkv[base + 256];
            vs[r * 34 + c]  = qkv[base + 512];
        }
    }
    __syncthreads();

    u64 qv[16];
    #pragma unroll
    for (int j = 0; j < 16; ++j) qv[j] = lds2(&qs[t * 34 + 2 * j]);
    for (int kr = 0; kr < 64; ++kr) {
        u64 acc = 0ULL;
        #pragma unroll
        for (int j = 0; j < 16; ++j) fma2(acc, qv[j], lds2(&ks_[kr * 34 + 2 * j]));
        float lo, hi; upk2(acc, lo, hi);
        ssm[t * 65 + kr] = lo + hi;           // scale folded into q
    }
    float mx = -1e30f;
    for (int kr = 0; kr < 64; ++kr) mx = fmaxf(mx, ssm[t * 65 + kr]);
    float sum = 0.f;
    for (int kr = 0; kr < 64; ++kr) {
        float e = __expf(ssm[t * 65 + kr] - mx);
        ssm[t * 65 + kr] = e; sum += e;
    }
    float inv = 1.f / sum;
    u64 o2[16];
    #pragma unroll
    for (int j = 0; j < 16; ++j) o2[j] = 0ULL;
    for (int kr = 0; kr < 64; ++kr) {
        float p = ssm[t * 65 + kr];
        u64 pd = pk2(p, p);
        #pragma unroll
        for (int j = 0; j < 16; ++j) fma2(o2[j], pd, lds2(&vs[kr * 34 + 2 * j]));
    }
    #pragma unroll
    for (int j = 0; j < 16; ++j) {
        float a, b; upk2(o2[j], a, b);
        qs[t * 34 + 2 * j] = a * inv; qs[t * 34 + 2 * j + 1] = b * inv;
    }
    __syncthreads();
    for (int i = 0; i < 32; ++i) {
        int e = t + 64 * i, r = e >> 5, c = e & 31;
        float v = qs[r * 34 + c];
        __nv_bfloat16 hb = __float2bfloat16(v);
        size_t dst = (size_t)(R + r) * 256 + h * 32 + c;
        oh[dst] = hb;
        ol[dst] = __float2bfloat16(v - __bfloat162float(hb));
    }
}

// ---- residual + final LN ----
__global__ __launch_bounds__(256)
void final_ln_kernel(const float* __restrict__ x, const float* __restrict__ b_out,
                     const float* __restrict__ g_o, const float* __restrict__ b_o,
                     float* __restrict__ y) {
    const float* z = (const float*)g_pool;
    int w = threadIdx.x >> 5, tx = threadIdx.x & 31;
    int r = blockIdx.x * 8 + w;
    int goff = row_goff(r);
    float v[8], s = 0.f, ss = 0.f;
    #pragma unroll
    for (int i = 0; i < 8; ++i) {
        int c = tx + 32 * i;
        v[i] = x[goff + c] + z[(size_t)r * 256 + c] + b_out[c];
        s += v[i]; ss += v[i] * v[i];
    }
    #pragma unroll
    for (int o = 16; o; o >>= 1) { s  += __shfl_xor_sync(0xffffffffu, s,  o);
                                   ss += __shfl_xor_sync(0xffffffffu, ss, o); }
    float mean = s * (1.f / 256.f);
    float inv  = rsqrtf(ss * (1.f / 256.f) - mean * mean + EPS);
    #pragma unroll
    for (int i = 0; i < 8; ++i) {
        int c = tx + 32 * i;
        y[goff + c] = (v[i] - mean) * inv * g_o[c] + b_o[c];
    }
}

extern "C" void kernel_launch(void* const* d_in, const int* in_sizes, int n_in,
                              void* d_out, int out_size) {
    (void)in_sizes; (void)n_in; (void)out_size;
    const float* x     = (const float*)d_in[0];
    const float* w_in  = (const float*)d_in[1];
    const float* b_in  = (const float*)d_in[2];
    const float* w_out = (const float*)d_in[3];
    const float* b_out = (const float*)d_in[4];
    const float* g_q   = (const float*)d_in[5];
    const float* b_q   = (const float*)d_in[6];
    const float* g_k   = (const float*)d_in[7];
    const float* b_k   = (const float*)d_in[8];
    const float* g_v   = (const float*)d_in[9];
    const float* b_v   = (const float*)d_in[10];
    const float* g_o   = (const float*)d_in[11];
    const float* b_o   = (const float*)d_in[12];
    float* y = (float*)d_out;

    cudaFuncSetAttribute(gemm_split_kernel, cudaFuncAttributeMaxDynamicSharedMemorySize, SMEM_GEMM);

    prep_w_kernel<<<768, 256>>>(w_in, b_in, g_q, b_q, g_k, b_k, g_v, b_v);
    prep_wo_kernel<<<256, 256>>>(w_out);
    ln_split_kernel<<<MT / 8, 256>>>(x);
    gemm_split_kernel<<<dim3(MT / 128, 6), 256, SMEM_GEMM>>>(0);
    attn_kernel<<<2048 * 8, 64>>>();
    gemm_split_kernel<<<dim3(MT / 128, 2), 256, SMEM_GEMM>>>(1);
    final_ln_kernel<<<MT / 8, 256>>>(x, b_out, g_o, b_o, y);
}

// round 12
// speedup vs baseline: 1.8946x; 1.0561x over previous
#include <cuda_runtime.h>
#include <cuda_bf16.h>
#include <math.h>
#include <stdint.h>

// WindowAttention via mma.sync (HMMA) bf16 hi/lo-split GEMMs + fp32 attention.
// B=32, 64x64, C=256, ws=8 -> MT=131072 token rows.
// R12: ldmatrix fragment loads + 2 CTAs/SM in the GEMM.

#define EPS 1e-5f
#define MT 131072

// scratch pool (aliased):
//  [0, 384MB)     qkv fp32 [MT][768]   ; later z fp32 [MT][256]
//  [384MB,448MB)  xh bf16 [MT][256]    ; later oh
//  [448MB,512MB)  xl bf16 [MT][256]    ; later ol
__device__ __align__(256) unsigned char g_pool[536870912ULL];

__device__ __nv_bfloat16 g_wh[768 * 256];
__device__ __nv_bfloat16 g_wl[768 * 256];
__device__ float         g_bias[768];
__device__ __nv_bfloat16 g_woh[256 * 256];
__device__ __nv_bfloat16 g_wol[256 * 256];

typedef unsigned long long u64;
typedef unsigned int u32;

__device__ __forceinline__ u64 pk2(float lo, float hi) {
    u64 r; asm("mov.b64 %0, {%1, %2};" : "=l"(r) : "f"(lo), "f"(hi)); return r;
}
__device__ __forceinline__ void upk2(u64 v, float& lo, float& hi) {
    asm("mov.b64 {%0, %1}, %2;" : "=f"(lo), "=f"(hi) : "l"(v));
}
__device__ __forceinline__ void fma2(u64& d, u64 a, u64 b) {
    asm("fma.rn.f32x2 %0, %1, %2, %3;" : "=l"(d) : "l"(a), "l"(b), "l"(d));
}
__device__ __forceinline__ u64 lds2(const float* p) { return *reinterpret_cast<const u64*>(p); }

__device__ __forceinline__ uint32_t smem_u32(const void* p) {
    uint32_t a;
    asm("{ .reg .u64 t; cvta.to.shared.u64 t, %1; cvt.u32.u64 %0, t; }" : "=r"(a) : "l"(p));
    return a;
}
__device__ __forceinline__ void cpa16(void* dst, const void* src) {
    asm volatile("cp.async.cg.shared.global [%0], [%1], 16;"
                 :: "r"(smem_u32(dst)), "l"(src) : "memory");
}
#define CP_COMMIT() asm volatile("cp.async.commit_group;" ::: "memory")
#define CP_WAIT(n)  asm volatile("cp.async.wait_group %0;" :: "n"(n) : "memory")

#define MMA16816(d, a, b) \
    asm volatile("mma.sync.aligned.m16n8k16.row.col.f32.bf16.bf16.f32 " \
        "{%0,%1,%2,%3}, {%4,%5,%6,%7}, {%8,%9}, {%0,%1,%2,%3};" \
        : "+f"((d)[0]), "+f"((d)[1]), "+f"((d)[2]), "+f"((d)[3]) \
        : "r"((a)[0]), "r"((a)[1]), "r"((a)[2]), "r"((a)[3]), \
          "r"((b)[0]), "r"((b)[1]))

#define LDM4(r, addr) \
    asm volatile("ldmatrix.sync.aligned.m8n8.x4.shared.b16 {%0,%1,%2,%3}, [%4];" \
        : "=r"((r)[0]), "=r"((r)[1]), "=r"((r)[2]), "=r"((r)[3]) : "r"(addr))

__device__ __forceinline__ int row_goff(int r) {
    int win = r >> 6, t = r & 63;
    int b = win >> 6, wh8 = (win >> 3) & 7, ww = win & 7;
    return ((b * 64 + wh8 * 8 + (t >> 3)) * 64 + ww * 8 + (t & 7)) * 256;
}

// ---- prep: fold LN affine (+q scale) into in_proj, split hi/lo bf16 ----
__global__ void prep_w_kernel(const float* __restrict__ w_in, const float* __restrict__ b_in,
                              const float* __restrict__ g_q, const float* __restrict__ b_q,
                              const float* __restrict__ g_k, const float* __restrict__ b_k,
                              const float* __restrict__ g_v, const float* __restrict__ b_v) {
    __shared__ float red[8];
    int col = blockIdx.x, k = threadIdx.x;
    const float* g; const float* b;
    if (col < 256)      { g = g_q; b = b_q; }
    else if (col < 512) { g = g_k; b = b_k; }
    else                { g = g_v; b = b_v; }
    const float f = (col < 256) ? 0.17677669529663689f : 1.0f;   // 1/sqrt(32)
    float w  = w_in[col * 256 + k];
    float wf = w * g[k] * f;
    __nv_bfloat16 hi = __float2bfloat16(wf);
    g_wh[col * 256 + k] = hi;
    g_wl[col * 256 + k] = __float2bfloat16(wf - __bfloat162float(hi));
    float p = w * b[k];
    #pragma unroll
    for (int o = 16; o; o >>= 1) p += __shfl_xor_sync(0xffffffffu, p, o);
    if ((k & 31) == 0) red[k >> 5] = p;
    __syncthreads();
    if (k < 8) {
        float s = red[k];
        #pragma unroll
        for (int o = 4; o; o >>= 1) s += __shfl_xor_sync(0xffu, s, o);
        if (k == 0) g_bias[col] = (b_in[col] + s) * f;
    }
}

__global__ void prep_wo_kernel(const float* __restrict__ w_out) {
    int idx = blockIdx.x * 256 + threadIdx.x;
    float v = w_out[idx];
    __nv_bfloat16 hi = __float2bfloat16(v);
    g_woh[idx] = hi;
    g_wol[idx] = __float2bfloat16(v - __bfloat162float(hi));
}

// ---- LN + hi/lo split ----
__global__ __launch_bounds__(256)
void ln_split_kernel(const float* __restrict__ x) {
    __nv_bfloat16* xh = (__nv_bfloat16*)(g_pool + 402653184ULL);
    __nv_bfloat16* xl = (__nv_bfloat16*)(g_pool + 469762048ULL);
    int w = threadIdx.x >> 5, tx = threadIdx.x & 31;
    int r = blockIdx.x * 8 + w;
    int goff = row_goff(r);
    float v[8], s = 0.f, ss = 0.f;
    #pragma unroll
    for (int i = 0; i < 8; ++i) { v[i] = x[goff + tx + 32 * i]; s += v[i]; ss += v[i] * v[i]; }
    #pragma unroll
    for (int o = 16; o; o >>= 1) { s  += __shfl_xor_sync(0xffffffffu, s,  o);
                                   ss += __shfl_xor_sync(0xffffffffu, ss, o); }
    float mean = s * (1.f / 256.f);
    float inv  = rsqrtf(ss * (1.f / 256.f) - mean * mean + EPS);
    #pragma unroll
    for (int i = 0; i < 8; ++i) {
        float xn = (v[i] - mean) * inv;
        __nv_bfloat16 hi = __float2bfloat16(xn);
        size_t dst = (size_t)r * 256 + tx + 32 * i;
        xh[dst] = hi;
        xl[dst] = __float2bfloat16(xn - __bfloat162float(hi));
    }
}

// ---- HMMA bf16-split GEMM: phase0 qkv = xn@Win^T+bias; phase1 z = o@Wout^T ----
// CTA 128x128 tile, 8 warps (2x4), warp tile 64x32. K=256 in 8 chunks of 32,
// cp.async double-buffered, ldmatrix fragment loads, 2 CTAs/SM.
static const int CHUNK_H = 128 * 40;              // halves per array per buffer
static const int SMEM_GEMM = 2 * 4 * CHUNK_H * 2; // 81920 B

__global__ __launch_bounds__(256, 2)
void gemm_split_kernel(int phase) {
    extern __shared__ __nv_bfloat16 smh[];
    const int tid = threadIdx.x, wid = tid >> 5, lane = tid & 31;
    const int gid = lane >> 2, tig = lane & 3;
    const int mw = wid >> 2, nw = wid & 3;        // warp grid 2x4
    const int mt = blockIdx.x, nt = blockIdx.y;

    const __nv_bfloat16* Asrc_h = (const __nv_bfloat16*)(g_pool + 402653184ULL);
    const __nv_bfloat16* Asrc_l = (const __nv_bfloat16*)(g_pool + 469762048ULL);
    const __nv_bfloat16* Bsrc_h = phase ? g_woh : g_wh;
    const __nv_bfloat16* Bsrc_l = phase ? g_wol : g_wl;
    float* out = (float*)g_pool;
    const int oc = phase ? 256 : 768;

    const __nv_bfloat16* srcs[4] = {
        Asrc_h + (size_t)(mt * 128) * 256,
        Asrc_l + (size_t)(mt * 128) * 256,
        Bsrc_h + (size_t)(nt * 128) * 256,
        Bsrc_l + (size_t)(nt * 128) * 256 };

    auto prefetch = [&](int kc, int buf) {
        __nv_bfloat16* base = smh + buf * (4 * CHUNK_H);
        #pragma unroll
        for (int t = 0; t < 8; ++t) {
            int idx = tid + t * 256;
            int arr = idx >> 9, e = idx & 511, row = e >> 2, seg = e & 3;
            cpa16(base + arr * CHUNK_H + row * 40 + seg * 8,
                  srcs[arr] + (size_t)row * 256 + kc * 32 + seg * 8);
        }
    };

    float acc[4][4][4];
    #pragma unroll
    for (int m = 0; m < 4; ++m)
        #pragma unroll
        for (int n = 0; n < 4; ++n)
            #pragma unroll
            for (int q = 0; q < 4; ++q) acc[m][n][q] = 0.f;

    // ldmatrix lane addressing: lanes 0-15 -> tile rows 0-15 (k lo 8),
    // lanes 16-31 -> rows 0-15 (k hi 8)
    const int lr = lane & 15, lk = lane >> 4;
    const u32 sbm = smem_u32(smh);
    const u32 CH  = (u32)(CHUNK_H * 2);                          // bytes per array
    const u32 aoff = (u32)(((mw * 64 + lr) * 40 + lk * 8) * 2);  // A m=0 frag byte off
    const u32 boff = (u32)(((nw * 32 + lr) * 40 + lk * 8) * 2);  // B pair=0 frag byte off

    prefetch(0, 0);
    CP_COMMIT();

    for (int kc = 0; kc < 8; ++kc) {
        if (kc + 1 < 8) prefetch(kc + 1, (kc + 1) & 1);
        CP_COMMIT();
        CP_WAIT(1);
        __syncthreads();
        const u32 base = sbm + (u32)((kc & 1) * (4 * CHUNK_H * 2));
        #pragma unroll
        for (int ks = 0; ks < 2; ++ks) {
            const u32 kb = (u32)(ks * 32);
            u32 Ah_[4][4], Al_[4][4], Bh_[2][4], Bl_[2][4];
            #pragma unroll
            for (int m = 0; m < 4; ++m) {
                LDM4(Ah_[m], base +          aoff + m * 1280 + kb);
                LDM4(Al_[m], base + CH +     aoff + m * 1280 + kb);
            }
            #pragma unroll
            for (int p = 0; p < 2; ++p) {
                LDM4(Bh_[p], base + 2 * CH + boff + p * 1280 + kb);
                LDM4(Bl_[p], base + 3 * CH + boff + p * 1280 + kb);
            }
            #pragma unroll
            for (int m = 0; m < 4; ++m)
                #pragma unroll
                for (int p = 0; p < 2; ++p)
                    #pragma unroll
                    for (int sub = 0; sub < 2; ++sub) {
                        u32 bh2[2] = { Bh_[p][sub], Bh_[p][sub + 2] };
                        u32 bl2[2] = { Bl_[p][sub], Bl_[p][sub + 2] };
                        float* d = acc[m][p * 2 + sub];
                        MMA16816(d, Ah_[m], bh2);   // hh
                        MMA16816(d, Ah_[m], bl2);   // hl
                        MMA16816(d, Al_[m], bh2);   // lh
                    }
        }
        __syncthreads();
    }

    // epilogue: direct global stores (8B pairs), + bias for phase0
    const bool has_bias = (phase == 0);
    #pragma unroll
    for (int m = 0; m < 4; ++m) {
        int row = mt * 128 + mw * 64 + m * 16 + gid;
        #pragma unroll
        for (int n = 0; n < 4; ++n) {
            int col = nt * 128 + nw * 32 + n * 8 + tig * 2;
            float b0 = 0.f, b1 = 0.f;
            if (has_bias) { b0 = g_bias[col]; b1 = g_bias[col + 1]; }
            float2 v0 = make_float2(acc[m][n][0] + b0, acc[m][n][1] + b1);
            float2 v1 = make_float2(acc[m][n][2] + b0, acc[m][n][3] + b1);
            *(float2*)(out + (size_t)row * oc + col)       = v0;
            *(float2*)(out + (size_t)(row + 8) * oc + col) = v1;
        }
    }
}

// ---- attention: CTA = win*8 + head, 64 threads, fp32 FFMA2 ----
__global__ __launch_bounds__(64)
void attn_kernel() {
    __shared__ float qs[64 * 34], ks_[64 * 34], vs[64 * 34], ssm[64 * 65];
    const float* qkv = (const float*)g_pool;
    __nv_bfloat16* oh = (__nv_bfloat16*)(g_pool + 402653184ULL);
    __nv_bfloat16* ol = (__nv_bfloat16*)(g_pool + 469762048ULL);

    int t = threadIdx.x;
    int win = blockIdx.x >> 3, h = blockIdx.x & 7;
    int R = win * 64;
    {
        int c = t & 31, r0 = t >> 5;
        for (int i = 0; i < 32; ++i) {
            int r = r0 + 2 * i;
            size_t base = (size_t)(R + r) * 768 + h * 32 + c;
            qs[r * 34 + c]  = qkv[base];
            ks_[r * 34 + c] = qkv[base + 256];
            vs[r * 34 + c]  = qkv[base + 512];
        }
    }
    __syncthreads();

    u64 qv[16];
    #pragma unroll
    for (int j = 0; j < 16; ++j) qv[j] = lds2(&qs[t * 34 + 2 * j]);
    for (int kr = 0; kr < 64; ++kr) {
        u64 acc = 0ULL;
        #pragma unroll
        for (int j = 0; j < 16; ++j) fma2(acc, qv[j], lds2(&ks_[kr * 34 + 2 * j]));
        float lo, hi; upk2(acc, lo, hi);
        ssm[t * 65 + kr] = lo + hi;           // scale folded into q
    }
    float mx = -1e30f;
    for (int kr = 0; kr < 64; ++kr) mx = fmaxf(mx, ssm[t * 65 + kr]);
    float sum = 0.f;
    for (int kr = 0; kr < 64; ++kr) {
        float e = __expf(ssm[t * 65 + kr] - mx);
        ssm[t * 65 + kr] = e; sum += e;
    }
    float inv = 1.f / sum;
    u64 o2[16];
    #pragma unroll
    for (int j = 0; j < 16; ++j) o2[j] = 0ULL;
    for (int kr = 0; kr < 64; ++kr) {
        float p = ssm[t * 65 + kr];
        u64 pd = pk2(p, p);
        #pragma unroll
        for (int j = 0; j < 16; ++j) fma2(o2[j], pd, lds2(&vs[kr * 34 + 2 * j]));
    }
    #pragma unroll
    for (int j = 0; j < 16; ++j) {
        float a, b; upk2(o2[j], a, b);
        qs[t * 34 + 2 * j] = a * inv; qs[t * 34 + 2 * j + 1] = b * inv;
    }
    __syncthreads();
    for (int i = 0; i < 32; ++i) {
        int e = t + 64 * i, r = e >> 5, c = e & 31;
        float v = qs[r * 34 + c];
        __nv_bfloat16 hb = __float2bfloat16(v);
        size_t dst = (size_t)(R + r) * 256 + h * 32 + c;
        oh[dst] = hb;
        ol[dst] = __float2bfloat16(v - __bfloat162float(hb));
    }
}

// ---- residual + final LN ----
__global__ __launch_bounds__(256)
void final_ln_kernel(const float* __restrict__ x, const float* __restrict__ b_out,
                     const float* __restrict__ g_o, const float* __restrict__ b_o,
                     float* __restrict__ y) {
    const float* z = (const float*)g_pool;
    int w = threadIdx.x >> 5, tx = threadIdx.x & 31;
    int r = blockIdx.x * 8 + w;
    int goff = row_goff(r);
    float v[8], s = 0.f, ss = 0.f;
    #pragma unroll
    for (int i = 0; i < 8; ++i) {
        int c = tx + 32 * i;
        v[i] = x[goff + c] + z[(size_t)r * 256 + c] + b_out[c];
        s += v[i]; ss += v[i] * v[i];
    }
    #pragma unroll
    for (int o = 16; o; o >>= 1) { s  += __shfl_xor_sync(0xffffffffu, s,  o);
                                   ss += __shfl_xor_sync(0xffffffffu, ss, o); }
    float mean = s * (1.f / 256.f);
    float inv  = rsqrtf(ss * (1.f / 256.f) - mean * mean + EPS);
    #pragma unroll
    for (int i = 0; i < 8; ++i) {
        int c = tx + 32 * i;
        y[goff + c] = (v[i] - mean) * inv * g_o[c] + b_o[c];
    }
}

extern "C" void kernel_launch(void* const* d_in, const int* in_sizes, int n_in,
                              void* d_out, int out_size) {
    (void)in_sizes; (void)n_in; (void)out_size;
    const float* x     = (const float*)d_in[0];
    const float* w_in  = (const float*)d_in[1];
    const float* b_in  = (const float*)d_in[2];
    const float* w_out = (const float*)d_in[3];
    const float* b_out = (const float*)d_in[4];
    const float* g_q   = (const float*)d_in[5];
    const float* b_q   = (const float*)d_in[6];
    const float* g_k   = (const float*)d_in[7];
    const float* b_k   = (const float*)d_in[8];
    const float* g_v   = (const float*)d_in[9];
    const float* b_v   = (const float*)d_in[10];
    const float* g_o   = (const float*)d_in[11];
    const float* b_o   = (const float*)d_in[12];
    float* y = (float*)d_out;

    cudaFuncSetAttribute(gemm_split_kernel, cudaFuncAttributeMaxDynamicSharedMemorySize, SMEM_GEMM);

    prep_w_kernel<<<768, 256>>>(w_in, b_in, g_q, b_q, g_k, b_k, g_v, b_v);
    prep_wo_kernel<<<256, 256>>>(w_out);
    ln_split_kernel<<<MT / 8, 256>>>(x);
    gemm_split_kernel<<<dim3(MT / 128, 6), 256, SMEM_GEMM>>>(0);
    attn_kernel<<<2048 * 8, 64>>>();
    gemm_split_kernel<<<dim3(MT / 128, 2), 256, SMEM_GEMM>>>(1);
    final_ln_kernel<<<MT / 8, 256>>>(x, b_out, g_o, b_o, y);
}

// round 13
// speedup vs baseline: 2.4201x; 1.2774x over previous
#include <cuda_runtime.h>
#include <cuda_fp16.h>
#include <math.h>
#include <stdint.h>

// WindowAttention via mma.sync HMMA fp16 2-term-split GEMMs + fp32 attention.
// B=32, 64x64, C=256, ws=8 -> MT=131072 token rows.
// R13: fp16 A-single / B-split (2 MMAs per tile instead of 3), L2-friendly
// grid order, hoisted prefetch addressing, register softmax in attention.

#define EPS 1e-5f
#define MT 131072

// scratch pool (aliased):
//  [0, 384MB)     qkv fp32 [MT][768]  ; later z fp32 [MT][256]
//  [384MB,448MB)  xh fp16 [MT][256]   ; later o fp16
__device__ __align__(256) unsigned char g_pool[469762048ULL];

__device__ __half g_wh[768 * 256];    // fp16 hi of folded in_proj (row n, k-major)
__device__ __half g_wl[768 * 256];    // fp16 lo
__device__ float  g_bias[768];
__device__ __half g_woh[256 * 256];
__device__ __half g_wol[256 * 256];

typedef unsigned long long u64;
typedef unsigned int u32;

__device__ __forceinline__ u64 pk2(float lo, float hi) {
    u64 r; asm("mov.b64 %0, {%1, %2};" : "=l"(r) : "f"(lo), "f"(hi)); return r;
}
__device__ __forceinline__ void upk2(u64 v, float& lo, float& hi) {
    asm("mov.b64 {%0, %1}, %2;" : "=f"(lo), "=f"(hi) : "l"(v));
}
__device__ __forceinline__ void fma2(u64& d, u64 a, u64 b) {
    asm("fma.rn.f32x2 %0, %1, %2, %3;" : "=l"(d) : "l"(a), "l"(b), "l"(d));
}
__device__ __forceinline__ u64 lds2(const float* p) { return *reinterpret_cast<const u64*>(p); }

__device__ __forceinline__ uint32_t smem_u32(const void* p) {
    uint32_t a;
    asm("{ .reg .u64 t; cvta.to.shared.u64 t, %1; cvt.u32.u64 %0, t; }" : "=r"(a) : "l"(p));
    return a;
}
#define CP_COMMIT() asm volatile("cp.async.commit_group;" ::: "memory")
#define CP_WAIT(n)  asm volatile("cp.async.wait_group %0;" :: "n"(n) : "memory")

#define MMA16816(d, a, b) \
    asm volatile("mma.sync.aligned.m16n8k16.row.col.f32.f16.f16.f32 " \
        "{%0,%1,%2,%3}, {%4,%5,%6,%7}, {%8,%9}, {%0,%1,%2,%3};" \
        : "+f"((d)[0]), "+f"((d)[1]), "+f"((d)[2]), "+f"((d)[3]) \
        : "r"((a)[0]), "r"((a)[1]), "r"((a)[2]), "r"((a)[3]), \
          "r"((b)[0]), "r"((b)[1]))

#define LDM4(r, addr) \
    asm volatile("ldmatrix.sync.aligned.m8n8.x4.shared.b16 {%0,%1,%2,%3}, [%4];" \
        : "=r"((r)[0]), "=r"((r)[1]), "=r"((r)[2]), "=r"((r)[3]) : "r"(addr))

__device__ __forceinline__ int row_goff(int r) {
    int win = r >> 6, t = r & 63;
    int b = win >> 6, wh8 = (win >> 3) & 7, ww = win & 7;
    return ((b * 64 + wh8 * 8 + (t >> 3)) * 64 + ww * 8 + (t & 7)) * 256;
}

// ---- prep: fold LN affine (+q scale) into in_proj, split hi/lo fp16 ----
__global__ void prep_w_kernel(const float* __restrict__ w_in, const float* __restrict__ b_in,
                              const float* __restrict__ g_q, const float* __restrict__ b_q,
                              const float* __restrict__ g_k, const float* __restrict__ b_k,
                              const float* __restrict__ g_v, const float* __restrict__ b_v) {
    __shared__ float red[8];
    int col = blockIdx.x, k = threadIdx.x;
    const float* g; const float* b;
    if (col < 256)      { g = g_q; b = b_q; }
    else if (col < 512) { g = g_k; b = b_k; }
    else                { g = g_v; b = b_v; }
    const float f = (col < 256) ? 0.17677669529663689f : 1.0f;   // 1/sqrt(32)
    float w  = w_in[col * 256 + k];
    float wf = w * g[k] * f;
    __half hi = __float2half_rn(wf);
    g_wh[col * 256 + k] = hi;
    g_wl[col * 256 + k] = __float2half_rn(wf - __half2float(hi));
    float p = w * b[k];
    #pragma unroll
    for (int o = 16; o; o >>= 1) p += __shfl_xor_sync(0xffffffffu, p, o);
    if ((k & 31) == 0) red[k >> 5] = p;
    __syncthreads();
    if (k < 8) {
        float s = red[k];
        #pragma unroll
        for (int o = 4; o; o >>= 1) s += __shfl_xor_sync(0xffu, s, o);
        if (k == 0) g_bias[col] = (b_in[col] + s) * f;
    }
}

__global__ void prep_wo_kernel(const float* __restrict__ w_out) {
    int idx = blockIdx.x * 256 + threadIdx.x;
    float v = w_out[idx];
    __half hi = __float2half_rn(v);
    g_woh[idx] = hi;
    g_wol[idx] = __float2half_rn(v - __half2float(hi));
}

// ---- LN + fp16 quantize ----
__global__ __launch_bounds__(256)
void ln_split_kernel(const float* __restrict__ x) {
    __half* xh = (__half*)(g_pool + 402653184ULL);
    int w = threadIdx.x >> 5, tx = threadIdx.x & 31;
    int r = blockIdx.x * 8 + w;
    int goff = row_goff(r);
    float v[8], s = 0.f, ss = 0.f;
    #pragma unroll
    for (int i = 0; i < 8; ++i) { v[i] = x[goff + tx + 32 * i]; s += v[i]; ss += v[i] * v[i]; }
    #pragma unroll
    for (int o = 16; o; o >>= 1) { s  += __shfl_xor_sync(0xffffffffu, s,  o);
                                   ss += __shfl_xor_sync(0xffffffffu, ss, o); }
    float mean = s * (1.f / 256.f);
    float inv  = rsqrtf(ss * (1.f / 256.f) - mean * mean + EPS);
    #pragma unroll
    for (int i = 0; i < 8; ++i)
        xh[(size_t)r * 256 + tx + 32 * i] = __float2half_rn((v[i] - mean) * inv);
}

// ---- HMMA fp16 2-term GEMM: phase0 qkv = xn@Win^T+bias; phase1 z = o@Wout^T ----
// CTA 128x128, 8 warps (2x4), warp tile 64x32. K=256 in 8 chunks of 32,
// cp.async double-buffered, ldmatrix, 2 CTAs/SM. A single fp16; B hi+lo fp16.
static const int CHUNK_H = 128 * 40;        // halves per array
static const int BUF_B   = 3 * CHUNK_H * 2; // 30720 B per buffer
static const int SMEM_GEMM = 2 * BUF_B;     // 61440 B

__global__ __launch_bounds__(256, 2)
void gemm_split_kernel(int phase) {
    extern __shared__ __half smh[];
    const int tid = threadIdx.x, wid = tid >> 5, lane = tid & 31;
    const int gid = lane >> 2, tig = lane & 3;
    const int mw = wid >> 2, nw = wid & 3;        // warp grid 2x4
    const int nt = blockIdx.x, mt = blockIdx.y;   // nt fast -> A reuse in L2

    const __half* Asrc = (const __half*)(g_pool + 402653184ULL) + (size_t)(mt * 128) * 256;
    const __half* Bh   = (phase ? g_woh : g_wh) + (size_t)(nt * 128) * 256;
    const __half* Bl   = (phase ? g_wol : g_wl) + (size_t)(nt * 128) * 256;
    float* out = (float*)g_pool;
    const int oc = phase ? 256 : 768;

    // prefetch setup: 1536 16B copies per chunk / 256 threads = 6 each
    const __half* psrc[6]; u32 pdst[6];
    const u32 sbm = smem_u32(smh);
    #pragma unroll
    for (int t = 0; t < 6; ++t) {
        int idx = tid + t * 256, arr = idx >> 9, e = idx & 511, row = e >> 2, seg = e & 3;
        const __half* s = (arr == 0) ? Asrc : ((arr == 1) ? Bh : Bl);
        psrc[t] = s + row * 256 + seg * 8;
        pdst[t] = sbm + (u32)((arr * CHUNK_H + row * 40 + seg * 8) * 2);
    }

    float acc[4][4][4];
    #pragma unroll
    for (int m = 0; m < 4; ++m)
        #pragma unroll
        for (int n = 0; n < 4; ++n)
            #pragma unroll
            for (int q = 0; q < 4; ++q) acc[m][n][q] = 0.f;

    const int lr = lane & 15, lk = lane >> 4;
    const u32 CHB  = (u32)(CHUNK_H * 2);
    const u32 aoff = (u32)(((mw * 64 + lr) * 40 + lk * 8) * 2);
    const u32 boff = (u32)(((nw * 32 + lr) * 40 + lk * 8) * 2);

    // prefetch chunk 0 into buffer 0
    #pragma unroll
    for (int t = 0; t < 6; ++t) {
        asm volatile("cp.async.cg.shared.global [%0], [%1], 16;"
                     :: "r"(pdst[t]), "l"(psrc[t]) : "memory");
        psrc[t] += 32;
    }
    CP_COMMIT();

    for (int kc = 0; kc < 8; ++kc) {
        if (kc < 7) {
            const u32 bo = (u32)(((kc + 1) & 1) * BUF_B);
            #pragma unroll
            for (int t = 0; t < 6; ++t) {
                asm volatile("cp.async.cg.shared.global [%0], [%1], 16;"
                             :: "r"(pdst[t] + bo), "l"(psrc[t]) : "memory");
                psrc[t] += 32;
            }
        }
        CP_COMMIT();
        CP_WAIT(1);
        __syncthreads();
        const u32 base = sbm + (u32)((kc & 1) * BUF_B);
        #pragma unroll
        for (int ks = 0; ks < 2; ++ks) {
            const u32 kb = (u32)(ks * 32);
            u32 A_[4][4], Bh_[2][4], Bl_[2][4];
            #pragma unroll
            for (int m = 0; m < 4; ++m)
                LDM4(A_[m], base + aoff + m * 1280 + kb);
            #pragma unroll
            for (int p = 0; p < 2; ++p) {
                LDM4(Bh_[p], base + CHB     + boff + p * 1280 + kb);
                LDM4(Bl_[p], base + 2 * CHB + boff + p * 1280 + kb);
            }
            #pragma unroll
            for (int m = 0; m < 4; ++m)
                #pragma unroll
                for (int p = 0; p < 2; ++p)
                    #pragma unroll
                    for (int sub = 0; sub < 2; ++sub) {
                        u32 bh2[2] = { Bh_[p][sub], Bh_[p][sub + 2] };
                        u32 bl2[2] = { Bl_[p][sub], Bl_[p][sub + 2] };
                        float* d = acc[m][p * 2 + sub];
                        MMA16816(d, A_[m], bh2);   // Ah x Bh
                        MMA16816(d, A_[m], bl2);   // Ah x Bl
                    }
        }
        __syncthreads();
    }

    // epilogue: direct global stores (8B pairs), + bias for phase0
    const bool has_bias = (phase == 0);
    #pragma unroll
    for (int m = 0; m < 4; ++m) {
        int row = mt * 128 + mw * 64 + m * 16 + gid;
        #pragma unroll
        for (int n = 0; n < 4; ++n) {
            int col = nt * 128 + nw * 32 + n * 8 + tig * 2;
            float b0 = 0.f, b1 = 0.f;
            if (has_bias) { b0 = g_bias[col]; b1 = g_bias[col + 1]; }
            float2 v0 = make_float2(acc[m][n][0] + b0, acc[m][n][1] + b1);
            float2 v1 = make_float2(acc[m][n][2] + b0, acc[m][n][3] + b1);
            *(float2*)(out + (size_t)row * oc + col)       = v0;
            *(float2*)(out + (size_t)(row + 8) * oc + col) = v1;
        }
    }
}

// ---- attention: CTA = win*8 + head, 64 threads, fp32 FFMA2, register softmax ----
__global__ __launch_bounds__(64)
void attn_kernel() {
    __shared__ float qs[64 * 34], ks_[64 * 34], vs[64 * 34];
    __shared__ __half os_[64 * 32];
    const float* qkv = (const float*)g_pool;
    __half* oh = (__half*)(g_pool + 402653184ULL);

    int t = threadIdx.x;
    int win = blockIdx.x >> 3, h = blockIdx.x & 7;
    int R = win * 64;
    {
        int c = t & 31, r0 = t >> 5;
        for (int i = 0; i < 32; ++i) {
            int r = r0 + 2 * i;
            size_t base = (size_t)(R + r) * 768 + h * 32 + c;
            qs[r * 34 + c]  = qkv[base];
            ks_[r * 34 + c] = qkv[base + 256];
            vs[r * 34 + c]  = qkv[base + 512];
        }
    }
    __syncthreads();

    u64 qv[16];
    #pragma unroll
    for (int j = 0; j < 16; ++j) qv[j] = lds2(&qs[t * 34 + 2 * j]);

    float sc[64];
    #pragma unroll
    for (int kr = 0; kr < 64; ++kr) {
        u64 acc = 0ULL;
        #pragma unroll
        for (int j = 0; j < 16; ++j) fma2(acc, qv[j], lds2(&ks_[kr * 34 + 2 * j]));
        float lo, hi; upk2(acc, lo, hi);
        sc[kr] = lo + hi;                 // scale folded into q
    }
    float mx = sc[0];
    #pragma unroll
    for (int kr = 1; kr < 64; ++kr) mx = fmaxf(mx, sc[kr]);
    float sum = 0.f;
    #pragma unroll
    for (int kr = 0; kr < 64; ++kr) { sc[kr] = __expf(sc[kr] - mx); sum += sc[kr]; }
    float inv = 1.f / sum;

    u64 o2[16];
    #pragma unroll
    for (int j = 0; j < 16; ++j) o2[j] = 0ULL;
    #pragma unroll
    for (int kr = 0; kr < 64; ++kr) {
        u64 pd = pk2(sc[kr], sc[kr]);
        #pragma unroll
        for (int j = 0; j < 16; ++j) fma2(o2[j], pd, lds2(&vs[kr * 34 + 2 * j]));
    }
    #pragma unroll
    for (int j = 0; j < 16; ++j) {
        float a, b; upk2(o2[j], a, b);
        os_[t * 32 + 2 * j]     = __float2half_rn(a * inv);
        os_[t * 32 + 2 * j + 1] = __float2half_rn(b * inv);
    }
    __syncthreads();
    // coalesced fp16 writeback: 1024 half2 words
    const __half2* osrc = (const __half2*)os_;
    for (int i = 0; i < 16; ++i) {
        int e = t + 64 * i, r = e >> 4, c = e & 15;
        ((__half2*)(oh + (size_t)(R + r) * 256 + h * 32))[c] = osrc[e];
    }
}

// ---- residual + final LN ----
__global__ __launch_bounds__(256)
void final_ln_kernel(const float* __restrict__ x, const float* __restrict__ b_out,
                     const float* __restrict__ g_o, const float* __restrict__ b_o,
                     float* __restrict__ y) {
    const float* z = (const float*)g_pool;
    int w = threadIdx.x >> 5, tx = threadIdx.x & 31;
    int r = blockIdx.x * 8 + w;
    int goff = row_goff(r);
    float v[8], s = 0.f, ss = 0.f;
    #pragma unroll
    for (int i = 0; i < 8; ++i) {
        int c = tx + 32 * i;
        v[i] = x[goff + c] + z[(size_t)r * 256 + c] + b_out[c];
        s += v[i]; ss += v[i] * v[i];
    }
    #pragma unroll
    for (int o = 16; o; o >>= 1) { s  += __shfl_xor_sync(0xffffffffu, s,  o);
                                   ss += __shfl_xor_sync(0xffffffffu, ss, o); }
    float mean = s * (1.f / 256.f);
    float inv  = rsqrtf(ss * (1.f / 256.f) - mean * mean + EPS);
    #pragma unroll
    for (int i = 0; i < 8; ++i) {
        int c = tx + 32 * i;
        y[goff + c] = (v[i] - mean) * inv * g_o[c] + b_o[c];
    }
}

extern "C" void kernel_launch(void* const* d_in, const int* in_sizes, int n_in,
                              void* d_out, int out_size) {
    (void)in_sizes; (void)n_in; (void)out_size;
    const float* x     = (const float*)d_in[0];
    const float* w_in  = (const float*)d_in[1];
    const float* b_in  = (const float*)d_in[2];
    const float* w_out = (const float*)d_in[3];
    const float* b_out = (const float*)d_in[4];
    const float* g_q   = (const float*)d_in[5];
    const float* b_q   = (const float*)d_in[6];
    const float* g_k   = (const float*)d_in[7];
    const float* b_k   = (const float*)d_in[8];
    const float* g_v   = (const float*)d_in[9];
    const float* b_v   = (const float*)d_in[10];
    const float* g_o   = (const float*)d_in[11];
    const float* b_o   = (const float*)d_in[12];
    float* y = (float*)d_out;

    cudaFuncSetAttribute(gemm_split_kernel, cudaFuncAttributeMaxDynamicSharedMemorySize, SMEM_GEMM);

    prep_w_kernel<<<768, 256>>>(w_in, b_in, g_q, b_q, g_k, b_k, g_v, b_v);
    prep_wo_kernel<<<256, 256>>>(w_out);
    ln_split_kernel<<<MT / 8, 256>>>(x);
    gemm_split_kernel<<<dim3(6, MT / 128), 256, SMEM_GEMM>>>(0);
    attn_kernel<<<2048 * 8, 64>>>();
    gemm_split_kernel<<<dim3(2, MT / 128), 256, SMEM_GEMM>>>(1);
    final_ln_kernel<<<MT / 8, 256>>>(x, b_out, g_o, b_o, y);
}

// round 14
// speedup vs baseline: 3.1755x; 1.3121x over previous
#include <cuda_runtime.h>
#include <cuda_fp16.h>
#include <math.h>
#include <stdint.h>

// WindowAttention: HMMA fp16 2-term-split GEMMs + HMMA fp16 attention.
// B=32, 64x64, C=256, ws=8 -> MT=131072 token rows.
// R14: qkv in fp16, attention on mma.sync (scores + PV), register softmax.

#define EPS 1e-5f
#define MT 131072

// scratch pool (aliased):
//  [0, 201M)      qkv fp16 [MT][768]
//  [201M, 335M)   z fp32 [MT][256]
//  [384M, 448M)   xh fp16 [MT][256]  ; later o fp16
__device__ __align__(256) unsigned char g_pool[469762048ULL];
#define OFF_QKV 0ULL
#define OFF_Z   201326592ULL
#define OFF_XH  402653184ULL

__device__ __half g_wh[768 * 256];
__device__ __half g_wl[768 * 256];
__device__ float  g_bias[768];
__device__ __half g_woh[256 * 256];
__device__ __half g_wol[256 * 256];

typedef unsigned long long u64;
typedef unsigned int u32;

__device__ __forceinline__ uint32_t smem_u32(const void* p) {
    uint32_t a;
    asm("{ .reg .u64 t; cvta.to.shared.u64 t, %1; cvt.u32.u64 %0, t; }" : "=r"(a) : "l"(p));
    return a;
}
#define CP_COMMIT() asm volatile("cp.async.commit_group;" ::: "memory")
#define CP_WAIT(n)  asm volatile("cp.async.wait_group %0;" :: "n"(n) : "memory")

#define MMA16816(d, a, b) \
    asm volatile("mma.sync.aligned.m16n8k16.row.col.f32.f16.f16.f32 " \
        "{%0,%1,%2,%3}, {%4,%5,%6,%7}, {%8,%9}, {%0,%1,%2,%3};" \
        : "+f"((d)[0]), "+f"((d)[1]), "+f"((d)[2]), "+f"((d)[3]) \
        : "r"((a)[0]), "r"((a)[1]), "r"((a)[2]), "r"((a)[3]), \
          "r"((b)[0]), "r"((b)[1]))

#define LDM4(r, addr) \
    asm volatile("ldmatrix.sync.aligned.m8n8.x4.shared.b16 {%0,%1,%2,%3}, [%4];" \
        : "=r"((r)[0]), "=r"((r)[1]), "=r"((r)[2]), "=r"((r)[3]) : "r"(addr))

#define LDM4T(r, addr) \
    asm volatile("ldmatrix.sync.aligned.m8n8.x4.trans.shared.b16 {%0,%1,%2,%3}, [%4];" \
        : "=r"((r)[0]), "=r"((r)[1]), "=r"((r)[2]), "=r"((r)[3]) : "r"(addr))

__device__ __forceinline__ u32 h2u(float a, float b) {
    __half2 t = __floats2half2_rn(a, b);
    return *(u32*)&t;
}

__device__ __forceinline__ int row_goff(int r) {
    int win = r >> 6, t = r & 63;
    int b = win >> 6, wh8 = (win >> 3) & 7, ww = win & 7;
    return ((b * 64 + wh8 * 8 + (t >> 3)) * 64 + ww * 8 + (t & 7)) * 256;
}

// ---- prep: fold LN affine (+q scale) into in_proj, split hi/lo fp16 ----
__global__ void prep_w_kernel(const float* __restrict__ w_in, const float* __restrict__ b_in,
                              const float* __restrict__ g_q, const float* __restrict__ b_q,
                              const float* __restrict__ g_k, const float* __restrict__ b_k,
                              const float* __restrict__ g_v, const float* __restrict__ b_v) {
    __shared__ float red[8];
    int col = blockIdx.x, k = threadIdx.x;
    const float* g; const float* b;
    if (col < 256)      { g = g_q; b = b_q; }
    else if (col < 512) { g = g_k; b = b_k; }
    else                { g = g_v; b = b_v; }
    const float f = (col < 256) ? 0.17677669529663689f : 1.0f;   // 1/sqrt(32)
    float w  = w_in[col * 256 + k];
    float wf = w * g[k] * f;
    __half hi = __float2half_rn(wf);
    g_wh[col * 256 + k] = hi;
    g_wl[col * 256 + k] = __float2half_rn(wf - __half2float(hi));
    float p = w * b[k];
    #pragma unroll
    for (int o = 16; o; o >>= 1) p += __shfl_xor_sync(0xffffffffu, p, o);
    if ((k & 31) == 0) red[k >> 5] = p;
    __syncthreads();
    if (k < 8) {
        float s = red[k];
        #pragma unroll
        for (int o = 4; o; o >>= 1) s += __shfl_xor_sync(0xffu, s, o);
        if (k == 0) g_bias[col] = (b_in[col] + s) * f;
    }
}

__global__ void prep_wo_kernel(const float* __restrict__ w_out) {
    int idx = blockIdx.x * 256 + threadIdx.x;
    float v = w_out[idx];
    __half hi = __float2half_rn(v);
    g_woh[idx] = hi;
    g_wol[idx] = __float2half_rn(v - __half2float(hi));
}

// ---- LN + fp16 quantize ----
__global__ __launch_bounds__(256)
void ln_split_kernel(const float* __restrict__ x) {
    __half* xh = (__half*)(g_pool + OFF_XH);
    int w = threadIdx.x >> 5, tx = threadIdx.x & 31;
    int r = blockIdx.x * 8 + w;
    int goff = row_goff(r);
    float v[8], s = 0.f, ss = 0.f;
    #pragma unroll
    for (int i = 0; i < 8; ++i) { v[i] = x[goff + tx + 32 * i]; s += v[i]; ss += v[i] * v[i]; }
    #pragma unroll
    for (int o = 16; o; o >>= 1) { s  += __shfl_xor_sync(0xffffffffu, s,  o);
                                   ss += __shfl_xor_sync(0xffffffffu, ss, o); }
    float mean = s * (1.f / 256.f);
    float inv  = rsqrtf(ss * (1.f / 256.f) - mean * mean + EPS);
    #pragma unroll
    for (int i = 0; i < 8; ++i)
        xh[(size_t)r * 256 + tx + 32 * i] = __float2half_rn((v[i] - mean) * inv);
}

// ---- HMMA fp16 2-term GEMM ----
// phase0: qkv(fp16) = xn@Win^T + bias ; phase1: z(fp32) = o@Wout^T
static const int CHUNK_H = 128 * 40;
static const int BUF_B   = 3 * CHUNK_H * 2;
static const int SMEM_GEMM = 2 * BUF_B;     // 61440 B

__global__ __launch_bounds__(256, 2)
void gemm_split_kernel(int phase) {
    extern __shared__ __half smh[];
    const int tid = threadIdx.x, wid = tid >> 5, lane = tid & 31;
    const int gid = lane >> 2, tig = lane & 3;
    const int mw = wid >> 2, nw = wid & 3;
    const int nt = blockIdx.x, mt = blockIdx.y;

    const __half* Asrc = (const __half*)(g_pool + OFF_XH) + (size_t)(mt * 128) * 256;
    const __half* Bh   = (phase ? g_woh : g_wh) + (size_t)(nt * 128) * 256;
    const __half* Bl   = (phase ? g_wol : g_wl) + (size_t)(nt * 128) * 256;

    const __half* psrc[6]; u32 pdst[6];
    const u32 sbm = smem_u32(smh);
    #pragma unroll
    for (int t = 0; t < 6; ++t) {
        int idx = tid + t * 256, arr = idx >> 9, e = idx & 511, row = e >> 2, seg = e & 3;
        const __half* s = (arr == 0) ? Asrc : ((arr == 1) ? Bh : Bl);
        psrc[t] = s + row * 256 + seg * 8;
        pdst[t] = sbm + (u32)((arr * CHUNK_H + row * 40 + seg * 8) * 2);
    }

    float acc[4][4][4];
    #pragma unroll
    for (int m = 0; m < 4; ++m)
        #pragma unroll
        for (int n = 0; n < 4; ++n)
            #pragma unroll
            for (int q = 0; q < 4; ++q) acc[m][n][q] = 0.f;

    const int lr = lane & 15, lk = lane >> 4;
    const u32 CHB  = (u32)(CHUNK_H * 2);
    const u32 aoff = (u32)(((mw * 64 + lr) * 40 + lk * 8) * 2);
    const u32 boff = (u32)(((nw * 32 + lr) * 40 + lk * 8) * 2);

    #pragma unroll
    for (int t = 0; t < 6; ++t) {
        asm volatile("cp.async.cg.shared.global [%0], [%1], 16;"
                     :: "r"(pdst[t]), "l"(psrc[t]) : "memory");
        psrc[t] += 32;
    }
    CP_COMMIT();

    for (int kc = 0; kc < 8; ++kc) {
        if (kc < 7) {
            const u32 bo = (u32)(((kc + 1) & 1) * BUF_B);
            #pragma unroll
            for (int t = 0; t < 6; ++t) {
                asm volatile("cp.async.cg.shared.global [%0], [%1], 16;"
                             :: "r"(pdst[t] + bo), "l"(psrc[t]) : "memory");
                psrc[t] += 32;
            }
        }
        CP_COMMIT();
        CP_WAIT(1);
        __syncthreads();
        const u32 base = sbm + (u32)((kc & 1) * BUF_B);
        #pragma unroll
        for (int ks = 0; ks < 2; ++ks) {
            const u32 kb = (u32)(ks * 32);
            u32 A_[4][4], Bh_[2][4], Bl_[2][4];
            #pragma unroll
            for (int m = 0; m < 4; ++m)
                LDM4(A_[m], base + aoff + m * 1280 + kb);
            #pragma unroll
            for (int p = 0; p < 2; ++p) {
                LDM4(Bh_[p], base + CHB     + boff + p * 1280 + kb);
                LDM4(Bl_[p], base + 2 * CHB + boff + p * 1280 + kb);
            }
            #pragma unroll
            for (int m = 0; m < 4; ++m)
                #pragma unroll
                for (int p = 0; p < 2; ++p)
                    #pragma unroll
                    for (int sub = 0; sub < 2; ++sub) {
                        u32 bh2[2] = { Bh_[p][sub], Bh_[p][sub + 2] };
                        u32 bl2[2] = { Bl_[p][sub], Bl_[p][sub + 2] };
                        float* d = acc[m][p * 2 + sub];
                        MMA16816(d, A_[m], bh2);
                        MMA16816(d, A_[m], bl2);
                    }
        }
        __syncthreads();
    }

    if (phase == 0) {
        __half* out = (__half*)(g_pool + OFF_QKV);
        #pragma unroll
        for (int m = 0; m < 4; ++m) {
            int row = mt * 128 + mw * 64 + m * 16 + gid;
            #pragma unroll
            for (int n = 0; n < 4; ++n) {
                int col = nt * 128 + nw * 32 + n * 8 + tig * 2;
                float b0 = g_bias[col], b1 = g_bias[col + 1];
                *(u32*)(out + (size_t)row * 768 + col) =
                    h2u(acc[m][n][0] + b0, acc[m][n][1] + b1);
                *(u32*)(out + (size_t)(row + 8) * 768 + col) =
                    h2u(acc[m][n][2] + b0, acc[m][n][3] + b1);
            }
        }
    } else {
        float* out = (float*)(g_pool + OFF_Z);
        #pragma unroll
        for (int m = 0; m < 4; ++m) {
            int row = mt * 128 + mw * 64 + m * 16 + gid;
            #pragma unroll
            for (int n = 0; n < 4; ++n) {
                int col = nt * 128 + nw * 32 + n * 8 + tig * 2;
                *(float2*)(out + (size_t)row * 256 + col) =
                    make_float2(acc[m][n][0], acc[m][n][1]);
                *(float2*)(out + (size_t)(row + 8) * 256 + col) =
                    make_float2(acc[m][n][2], acc[m][n][3]);
            }
        }
    }
}

// ---- attention: CTA = window, 8 warps = 8 heads, HMMA fp16 ----
// smem: qkv window [64][776] fp16 = 99328 B (pad 776 -> conflict-free ldmatrix)
static const int SMEM_ATTN = 64 * 776 * 2;

__global__ __launch_bounds__(256, 2)
void attn_kernel() {
    extern __shared__ __half sk[];
    const __half* qkv = (const __half*)(g_pool + OFF_QKV);
    __half* o = (__half*)(g_pool + OFF_XH);

    const int tid = threadIdx.x, wid = tid >> 5, lane = tid & 31;
    const int gid = lane >> 2, tig = lane & 3;
    const int R = blockIdx.x * 64;

    // stage the whole window's qkv (64 rows x 768 halves)
    {
        const uint4* src = (const uint4*)(qkv + (size_t)R * 768);
        for (int i = tid; i < 6144; i += 256) {
            int r = i / 96, c = i % 96;
            *(uint4*)(sk + r * 776 + c * 8) = src[(size_t)r * 96 + c];
        }
    }
    __syncthreads();

    const int h = wid;
    const u32 sb = smem_u32(sk);
    const int lr = lane & 15, lk = lane >> 4;
    const u32 qaddr = sb + (u32)((lr * 776 + h * 32 + lk * 8) * 2);
    const u32 kaddr = sb + (u32)((lr * 776 + 256 + h * 32 + lk * 8) * 2);
    const u32 vaddr = sb + (u32)((((lane & 7) + ((lane >> 3) & 1) * 8) * 776
                                  + 512 + h * 32 + (lane >> 4) * 8) * 2);

    // preload V^T fragments: rv[t][g]: toks 16t..+15, dims 16g..+15
    u32 rv[4][2][4];
    #pragma unroll
    for (int t = 0; t < 4; ++t)
        #pragma unroll
        for (int g = 0; g < 2; ++g)
            LDM4T(rv[t][g], vaddr + (u32)((t * 16 * 776 + g * 16) * 2));

    const u32 ROW16 = (u32)(16 * 776 * 2);

    for (int m = 0; m < 4; ++m) {
        // Q fragments for this m-tile (k = dims 0-15, 16-31)
        u32 QA[2][4];
        LDM4(QA[0], qaddr + m * ROW16);
        LDM4(QA[1], qaddr + m * ROW16 + 32);

        // scores S = Q.K^T : 8 n-tiles
        float S[8][4];
        #pragma unroll
        for (int n = 0; n < 8; ++n)
            #pragma unroll
            for (int q = 0; q < 4; ++q) S[n][q] = 0.f;
        #pragma unroll
        for (int p = 0; p < 4; ++p) {
            u32 kb0[4], kb1[4];
            LDM4(kb0, kaddr + p * ROW16);
            LDM4(kb1, kaddr + p * ROW16 + 32);
            #pragma unroll
            for (int sub = 0; sub < 2; ++sub) {
                u32 p0[2] = { kb0[sub], kb0[sub + 2] };
                u32 p1[2] = { kb1[sub], kb1[sub + 2] };
                MMA16816(S[p * 2 + sub], QA[0], p0);
                MMA16816(S[p * 2 + sub], QA[1], p1);
            }
        }

        // softmax on accumulator layout (rows gid / gid+8)
        float inv0, inv1;
        {
            float mx0 = -1e30f, mx1 = -1e30f;
            #pragma unroll
            for (int n = 0; n < 8; ++n) {
                mx0 = fmaxf(mx0, fmaxf(S[n][0], S[n][1]));
                mx1 = fmaxf(mx1, fmaxf(S[n][2], S[n][3]));
            }
            #pragma unroll
            for (int d = 1; d <= 2; d <<= 1) {
                mx0 = fmaxf(mx0, __shfl_xor_sync(0xffffffffu, mx0, d));
                mx1 = fmaxf(mx1, __shfl_xor_sync(0xffffffffu, mx1, d));
            }
            float s0 = 0.f, s1 = 0.f;
            #pragma unroll
            for (int n = 0; n < 8; ++n) {
                S[n][0] = __expf(S[n][0] - mx0); s0 += S[n][0];
                S[n][1] = __expf(S[n][1] - mx0); s0 += S[n][1];
                S[n][2] = __expf(S[n][2] - mx1); s1 += S[n][2];
                S[n][3] = __expf(S[n][3] - mx1); s1 += S[n][3];
            }
            #pragma unroll
            for (int d = 1; d <= 2; d <<= 1) {
                s0 += __shfl_xor_sync(0xffffffffu, s0, d);
                s1 += __shfl_xor_sync(0xffffffffu, s1, d);
            }
            inv0 = 1.f / s0; inv1 = 1.f / s1;
        }

        // O = P.V : 4 n-tiles (dims), K = 64 toks in 4 k-steps
        float O[4][4];
        #pragma unroll
        for (int n = 0; n < 4; ++n)
            #pragma unroll
            for (int q = 0; q < 4; ++q) O[n][q] = 0.f;
        #pragma unroll
        for (int t = 0; t < 4; ++t) {
            u32 PA[4];
            PA[0] = h2u(S[2 * t][0],     S[2 * t][1]);
            PA[1] = h2u(S[2 * t][2],     S[2 * t][3]);
            PA[2] = h2u(S[2 * t + 1][0], S[2 * t + 1][1]);
            PA[3] = h2u(S[2 * t + 1][2], S[2 * t + 1][3]);
            #pragma unroll
            for (int n = 0; n < 4; ++n) {
                u32 vp[2] = { rv[t][n >> 1][(n & 1) * 2], rv[t][n >> 1][(n & 1) * 2 + 1] };
                MMA16816(O[n], PA, vp);
            }
        }

        // scale + store fp16
        int row0 = R + m * 16 + gid;
        #pragma unroll
        for (int n = 0; n < 4; ++n) {
            int col = h * 32 + n * 8 + tig * 2;
            *(u32*)(o + (size_t)row0 * 256 + col) = h2u(O[n][0] * inv0, O[n][1] * inv0);
            *(u32*)(o + (size_t)(row0 + 8) * 256 + col) = h2u(O[n][2] * inv1, O[n][3] * inv1);
        }
    }
}

// ---- residual + final LN ----
__global__ __launch_bounds__(256)
void final_ln_kernel(const float* __restrict__ x, const float* __restrict__ b_out,
                     const float* __restrict__ g_o, const float* __restrict__ b_o,
                     float* __restrict__ y) {
    const float* z = (const float*)(g_pool + OFF_Z);
    int w = threadIdx.x >> 5, tx = threadIdx.x & 31;
    int r = blockIdx.x * 8 + w;
    int goff = row_goff(r);
    float v[8], s = 0.f, ss = 0.f;
    #pragma unroll
    for (int i = 0; i < 8; ++i) {
        int c = tx + 32 * i;
        v[i] = x[goff + c] + z[(size_t)r * 256 + c] + b_out[c];
        s += v[i]; ss += v[i] * v[i];
    }
    #pragma unroll
    for (int o = 16; o; o >>= 1) { s  += __shfl_xor_sync(0xffffffffu, s,  o);
                                   ss += __shfl_xor_sync(0xffffffffu, ss, o); }
    float mean = s * (1.f / 256.f);
    float inv  = rsqrtf(ss * (1.f / 256.f) - mean * mean + EPS);
    #pragma unroll
    for (int i = 0; i < 8; ++i) {
        int c = tx + 32 * i;
        y[goff + c] = (v[i] - mean) * inv * g_o[c] + b_o[c];
    }
}

extern "C" void kernel_launch(void* const* d_in, const int* in_sizes, int n_in,
                              void* d_out, int out_size) {
    (void)in_sizes; (void)n_in; (void)out_size;
    const float* x     = (const float*)d_in[0];
    const float* w_in  = (const float*)d_in[1];
    const float* b_in  = (const float*)d_in[2];
    const float* w_out = (const float*)d_in[3];
    const float* b_out = (const float*)d_in[4];
    const float* g_q   = (const float*)d_in[5];
    const float* b_q   = (const float*)d_in[6];
    const float* g_k   = (const float*)d_in[7];
    const float* b_k   = (const float*)d_in[8];
    const float* g_v   = (const float*)d_in[9];
    const float* b_v   = (const float*)d_in[10];
    const float* g_o   = (const float*)d_in[11];
    const float* b_o   = (const float*)d_in[12];
    float* y = (float*)d_out;

    cudaFuncSetAttribute(gemm_split_kernel, cudaFuncAttributeMaxDynamicSharedMemorySize, SMEM_GEMM);
    cudaFuncSetAttribute(attn_kernel, cudaFuncAttributeMaxDynamicSharedMemorySize, SMEM_ATTN);

    prep_w_kernel<<<768, 256>>>(w_in, b_in, g_q, b_q, g_k, b_k, g_v, b_v);
    prep_wo_kernel<<<256, 256>>>(w_out);
    ln_split_kernel<<<MT / 8, 256>>>(x);
    gemm_split_kernel<<<dim3(6, MT / 128), 256, SMEM_GEMM>>>(0);
    attn_kernel<<<2048, 256, SMEM_ATTN>>>();
    gemm_split_kernel<<<dim3(2, MT / 128), 256, SMEM_GEMM>>>(1);
    final_ln_kernel<<<MT / 8, 256>>>(x, b_out, g_o, b_o, y);
}

// round 15
// speedup vs baseline: 4.4563x; 1.4033x over previous
#include <cuda_runtime.h>
#include <cuda_fp16.h>
#include <math.h>
#include <stdint.h>

// WindowAttention: HMMA fp16 single-term GEMMs + HMMA fp16 attention.
// B=32, 64x64, C=256, ws=8 -> MT=131072 token rows.
// R15: dropped weight-lo split term (halves MMA count), K-chunk 64.

#define EPS 1e-5f
#define MT 131072

// scratch pool (aliased):
//  [0, 201M)      qkv fp16 [MT][768]
//  [201M, 335M)   z fp32 [MT][256]
//  [384M, 448M)   xh fp16 [MT][256]  ; later o fp16
__device__ __align__(256) unsigned char g_pool[469762048ULL];
#define OFF_QKV 0ULL
#define OFF_Z   201326592ULL
#define OFF_XH  402653184ULL

__device__ __half g_wh[768 * 256];    // folded in_proj fp16 (row n, k-major)
__device__ float  g_bias[768];
__device__ __half g_woh[256 * 256];   // w_out fp16

typedef unsigned long long u64;
typedef unsigned int u32;

__device__ __forceinline__ uint32_t smem_u32(const void* p) {
    uint32_t a;
    asm("{ .reg .u64 t; cvta.to.shared.u64 t, %1; cvt.u32.u64 %0, t; }" : "=r"(a) : "l"(p));
    return a;
}
#define CP_COMMIT() asm volatile("cp.async.commit_group;" ::: "memory")
#define CP_WAIT(n)  asm volatile("cp.async.wait_group %0;" :: "n"(n) : "memory")

#define MMA16816(d, a, b) \
    asm volatile("mma.sync.aligned.m16n8k16.row.col.f32.f16.f16.f32 " \
        "{%0,%1,%2,%3}, {%4,%5,%6,%7}, {%8,%9}, {%0,%1,%2,%3};" \
        : "+f"((d)[0]), "+f"((d)[1]), "+f"((d)[2]), "+f"((d)[3]) \
        : "r"((a)[0]), "r"((a)[1]), "r"((a)[2]), "r"((a)[3]), \
          "r"((b)[0]), "r"((b)[1]))

#define LDM4(r, addr) \
    asm volatile("ldmatrix.sync.aligned.m8n8.x4.shared.b16 {%0,%1,%2,%3}, [%4];" \
        : "=r"((r)[0]), "=r"((r)[1]), "=r"((r)[2]), "=r"((r)[3]) : "r"(addr))

#define LDM4T(r, addr) \
    asm volatile("ldmatrix.sync.aligned.m8n8.x4.trans.shared.b16 {%0,%1,%2,%3}, [%4];" \
        : "=r"((r)[0]), "=r"((r)[1]), "=r"((r)[2]), "=r"((r)[3]) : "r"(addr))

__device__ __forceinline__ u32 h2u(float a, float b) {
    __half2 t = __floats2half2_rn(a, b);
    return *(u32*)&t;
}

__device__ __forceinline__ int row_goff(int r) {
    int win = r >> 6, t = r & 63;
    int b = win >> 6, wh8 = (win >> 3) & 7, ww = win & 7;
    return ((b * 64 + wh8 * 8 + (t >> 3)) * 64 + ww * 8 + (t & 7)) * 256;
}

// ---- prep: fold LN affine (+q scale) into in_proj fp16 ----
__global__ void prep_w_kernel(const float* __restrict__ w_in, const float* __restrict__ b_in,
                              const float* __restrict__ g_q, const float* __restrict__ b_q,
                              const float* __restrict__ g_k, const float* __restrict__ b_k,
                              const float* __restrict__ g_v, const float* __restrict__ b_v) {
    __shared__ float red[8];
    int col = blockIdx.x, k = threadIdx.x;
    const float* g; const float* b;
    if (col < 256)      { g = g_q; b = b_q; }
    else if (col < 512) { g = g_k; b = b_k; }
    else                { g = g_v; b = b_v; }
    const float f = (col < 256) ? 0.17677669529663689f : 1.0f;   // 1/sqrt(32)
    float w  = w_in[col * 256 + k];
    g_wh[col * 256 + k] = __float2half_rn(w * g[k] * f);
    float p = w * b[k];
    #pragma unroll
    for (int o = 16; o; o >>= 1) p += __shfl_xor_sync(0xffffffffu, p, o);
    if ((k & 31) == 0) red[k >> 5] = p;
    __syncthreads();
    if (k < 8) {
        float s = red[k];
        #pragma unroll
        for (int o = 4; o; o >>= 1) s += __shfl_xor_sync(0xffu, s, o);
        if (k == 0) g_bias[col] = (b_in[col] + s) * f;
    }
}

__global__ void prep_wo_kernel(const float* __restrict__ w_out) {
    int idx = blockIdx.x * 256 + threadIdx.x;
    g_woh[idx] = __float2half_rn(w_out[idx]);
}

// ---- LN + fp16 quantize ----
__global__ __launch_bounds__(256)
void ln_split_kernel(const float* __restrict__ x) {
    __half* xh = (__half*)(g_pool + OFF_XH);
    int w = threadIdx.x >> 5, tx = threadIdx.x & 31;
    int r = blockIdx.x * 8 + w;
    int goff = row_goff(r);
    float v[8], s = 0.f, ss = 0.f;
    #pragma unroll
    for (int i = 0; i < 8; ++i) { v[i] = x[goff + tx + 32 * i]; s += v[i]; ss += v[i] * v[i]; }
    #pragma unroll
    for (int o = 16; o; o >>= 1) { s  += __shfl_xor_sync(0xffffffffu, s,  o);
                                   ss += __shfl_xor_sync(0xffffffffu, ss, o); }
    float mean = s * (1.f / 256.f);
    float inv  = rsqrtf(ss * (1.f / 256.f) - mean * mean + EPS);
    #pragma unroll
    for (int i = 0; i < 8; ++i)
        xh[(size_t)r * 256 + tx + 32 * i] = __float2half_rn((v[i] - mean) * inv);
}

// ---- HMMA fp16 GEMM: phase0 qkv(fp16) = xn@Win^T+bias; phase1 z(fp32) = o@Wout^T ----
// CTA 128x128, 8 warps (2x4), warp tile 64x32. K=256 in 4 chunks of 64,
// cp.async double-buffered, ldmatrix, 2 CTAs/SM. Row stride 72 halves.
static const int ROWH  = 72;
static const int ARR_H = 128 * ROWH;          // 9216 halves per array
static const int BUF_H = 2 * ARR_H;           // A + B
static const int SMEM_GEMM = 2 * BUF_H * 2;   // 73728 B

__global__ __launch_bounds__(256, 2)
void gemm_split_kernel(int phase) {
    extern __shared__ __half smh[];
    const int tid = threadIdx.x, wid = tid >> 5, lane = tid & 31;
    const int gid = lane >> 2, tig = lane & 3;
    const int mw = wid >> 2, nw = wid & 3;
    const int nt = blockIdx.x, mt = blockIdx.y;

    const __half* Asrc = (const __half*)(g_pool + OFF_XH) + (size_t)(mt * 128) * 256;
    const __half* Bsrc = (phase ? g_woh : g_wh) + (size_t)(nt * 128) * 256;

    // prefetch: 2048 16B copies per 64-chunk / 256 threads = 8 each
    const __half* psrc[8]; u32 pdst[8];
    const u32 sbm = smem_u32(smh);
    #pragma unroll
    for (int t = 0; t < 8; ++t) {
        int idx = tid + t * 256, arr = idx >> 10, e = idx & 1023, row = e >> 3, seg = e & 7;
        psrc[t] = (arr ? Bsrc : Asrc) + row * 256 + seg * 8;
        pdst[t] = sbm + (u32)((arr * ARR_H + row * ROWH + seg * 8) * 2);
    }

    float acc[4][4][4];
    #pragma unroll
    for (int m = 0; m < 4; ++m)
        #pragma unroll
        for (int n = 0; n < 4; ++n)
            #pragma unroll
            for (int q = 0; q < 4; ++q) acc[m][n][q] = 0.f;

    const int lr = lane & 15, lk = lane >> 4;
    const u32 aoff = (u32)(((mw * 64 + lr) * ROWH + lk * 8) * 2);
    const u32 boff = (u32)(ARR_H * 2 + ((nw * 32 + lr) * ROWH + lk * 8) * 2);
    const u32 BUF_B = (u32)(BUF_H * 2);

    #pragma unroll
    for (int t = 0; t < 8; ++t) {
        asm volatile("cp.async.cg.shared.global [%0], [%1], 16;"
                     :: "r"(pdst[t]), "l"(psrc[t]) : "memory");
        psrc[t] += 64;
    }
    CP_COMMIT();

    for (int kc = 0; kc < 4; ++kc) {
        if (kc < 3) {
            const u32 bo = ((kc + 1) & 1) * BUF_B;
            #pragma unroll
            for (int t = 0; t < 8; ++t) {
                asm volatile("cp.async.cg.shared.global [%0], [%1], 16;"
                             :: "r"(pdst[t] + bo), "l"(psrc[t]) : "memory");
                psrc[t] += 64;
            }
        }
        CP_COMMIT();
        CP_WAIT(1);
        __syncthreads();
        const u32 base = sbm + (kc & 1) * BUF_B;
        #pragma unroll
        for (int ks = 0; ks < 4; ++ks) {
            const u32 kb = (u32)(ks * 32);
            u32 A_[4][4], B_[2][4];
            #pragma unroll
            for (int m = 0; m < 4; ++m)
                LDM4(A_[m], base + aoff + m * (16 * ROWH * 2) + kb);
            #pragma unroll
            for (int p = 0; p < 2; ++p)
                LDM4(B_[p], base + boff + p * (16 * ROWH * 2) + kb);
            #pragma unroll
            for (int m = 0; m < 4; ++m)
                #pragma unroll
                for (int p = 0; p < 2; ++p)
                    #pragma unroll
                    for (int sub = 0; sub < 2; ++sub) {
                        u32 b2[2] = { B_[p][sub], B_[p][sub + 2] };
                        MMA16816(acc[m][p * 2 + sub], A_[m], b2);
                    }
        }
        __syncthreads();
    }

    if (phase == 0) {
        __half* out = (__half*)(g_pool + OFF_QKV);
        #pragma unroll
        for (int m = 0; m < 4; ++m) {
            int row = mt * 128 + mw * 64 + m * 16 + gid;
            #pragma unroll
            for (int n = 0; n < 4; ++n) {
                int col = nt * 128 + nw * 32 + n * 8 + tig * 2;
                float b0 = g_bias[col], b1 = g_bias[col + 1];
                *(u32*)(out + (size_t)row * 768 + col) =
                    h2u(acc[m][n][0] + b0, acc[m][n][1] + b1);
                *(u32*)(out + (size_t)(row + 8) * 768 + col) =
                    h2u(acc[m][n][2] + b0, acc[m][n][3] + b1);
            }
        }
    } else {
        float* out = (float*)(g_pool + OFF_Z);
        #pragma unroll
        for (int m = 0; m < 4; ++m) {
            int row = mt * 128 + mw * 64 + m * 16 + gid;
            #pragma unroll
            for (int n = 0; n < 4; ++n) {
                int col = nt * 128 + nw * 32 + n * 8 + tig * 2;
                *(float2*)(out + (size_t)row * 256 + col) =
                    make_float2(acc[m][n][0], acc[m][n][1]);
                *(float2*)(out + (size_t)(row + 8) * 256 + col) =
                    make_float2(acc[m][n][2], acc[m][n][3]);
            }
        }
    }
}

// ---- attention: CTA = window, 8 warps = 8 heads, HMMA fp16 ----
static const int SMEM_ATTN = 64 * 776 * 2;   // pad 776 -> conflict-free ldmatrix

__global__ __launch_bounds__(256, 2)
void attn_kernel() {
    extern __shared__ __half sk[];
    const __half* qkv = (const __half*)(g_pool + OFF_QKV);
    __half* o = (__half*)(g_pool + OFF_XH);

    const int tid = threadIdx.x, wid = tid >> 5, lane = tid & 31;
    const int gid = lane >> 2, tig = lane & 3;
    const int R = blockIdx.x * 64;

    {
        const uint4* src = (const uint4*)(qkv + (size_t)R * 768);
        for (int i = tid; i < 6144; i += 256) {
            int r = i / 96, c = i % 96;
            *(uint4*)(sk + r * 776 + c * 8) = src[(size_t)r * 96 + c];
        }
    }
    __syncthreads();

    const int h = wid;
    const u32 sb = smem_u32(sk);
    const int lr = lane & 15, lk = lane >> 4;
    const u32 qaddr = sb + (u32)((lr * 776 + h * 32 + lk * 8) * 2);
    const u32 kaddr = sb + (u32)((lr * 776 + 256 + h * 32 + lk * 8) * 2);
    const u32 vaddr = sb + (u32)((((lane & 7) + ((lane >> 3) & 1) * 8) * 776
                                  + 512 + h * 32 + (lane >> 4) * 8) * 2);

    u32 rv[4][2][4];
    #pragma unroll
    for (int t = 0; t < 4; ++t)
        #pragma unroll
        for (int g = 0; g < 2; ++g)
            LDM4T(rv[t][g], vaddr + (u32)((t * 16 * 776 + g * 16) * 2));

    const u32 ROW16 = (u32)(16 * 776 * 2);

    for (int m = 0; m < 4; ++m) {
        u32 QA[2][4];
        LDM4(QA[0], qaddr + m * ROW16);
        LDM4(QA[1], qaddr + m * ROW16 + 32);

        float S[8][4];
        #pragma unroll
        for (int n = 0; n < 8; ++n)
            #pragma unroll
            for (int q = 0; q < 4; ++q) S[n][q] = 0.f;
        #pragma unroll
        for (int p = 0; p < 4; ++p) {
            u32 kb0[4], kb1[4];
            LDM4(kb0, kaddr + p * ROW16);
            LDM4(kb1, kaddr + p * ROW16 + 32);
            #pragma unroll
            for (int sub = 0; sub < 2; ++sub) {
                u32 p0[2] = { kb0[sub], kb0[sub + 2] };
                u32 p1[2] = { kb1[sub], kb1[sub + 2] };
                MMA16816(S[p * 2 + sub], QA[0], p0);
                MMA16816(S[p * 2 + sub], QA[1], p1);
            }
        }

        float inv0, inv1;
        {
            float mx0 = -1e30f, mx1 = -1e30f;
            #pragma unroll
            for (int n = 0; n < 8; ++n) {
                mx0 = fmaxf(mx0, fmaxf(S[n][0], S[n][1]));
                mx1 = fmaxf(mx1, fmaxf(S[n][2], S[n][3]));
            }
            #pragma unroll
            for (int d = 1; d <= 2; d <<= 1) {
                mx0 = fmaxf(mx0, __shfl_xor_sync(0xffffffffu, mx0, d));
                mx1 = fmaxf(mx1, __shfl_xor_sync(0xffffffffu, mx1, d));
            }
            float s0 = 0.f, s1 = 0.f;
            #pragma unroll
            for (int n = 0; n < 8; ++n) {
                S[n][0] = __expf(S[n][0] - mx0); s0 += S[n][0];
                S[n][1] = __expf(S[n][1] - mx0); s0 += S[n][1];
                S[n][2] = __expf(S[n][2] - mx1); s1 += S[n][2];
                S[n][3] = __expf(S[n][3] - mx1); s1 += S[n][3];
            }
            #pragma unroll
            for (int d = 1; d <= 2; d <<= 1) {
                s0 += __shfl_xor_sync(0xffffffffu, s0, d);
                s1 += __shfl_xor_sync(0xffffffffu, s1, d);
            }
            inv0 = 1.f / s0; inv1 = 1.f / s1;
        }

        float O[4][4];
        #pragma unroll
        for (int n = 0; n < 4; ++n)
            #pragma unroll
            for (int q = 0; q < 4; ++q) O[n][q] = 0.f;
        #pragma unroll
        for (int t = 0; t < 4; ++t) {
            u32 PA[4];
            PA[0] = h2u(S[2 * t][0],     S[2 * t][1]);
            PA[1] = h2u(S[2 * t][2],     S[2 * t][3]);
            PA[2] = h2u(S[2 * t + 1][0], S[2 * t + 1][1]);
            PA[3] = h2u(S[2 * t + 1][2], S[2 * t + 1][3]);
            #pragma unroll
            for (int n = 0; n < 4; ++n) {
                u32 vp[2] = { rv[t][n >> 1][(n & 1) * 2], rv[t][n >> 1][(n & 1) * 2 + 1] };
                MMA16816(O[n], PA, vp);
            }
        }

        int row0 = R + m * 16 + gid;
        #pragma unroll
        for (int n = 0; n < 4; ++n) {
            int col = h * 32 + n * 8 + tig * 2;
            *(u32*)(o + (size_t)row0 * 256 + col) = h2u(O[n][0] * inv0, O[n][1] * inv0);
            *(u32*)(o + (size_t)(row0 + 8) * 256 + col) = h2u(O[n][2] * inv1, O[n][3] * inv1);
        }
    }
}

// ---- residual + final LN ----
__global__ __launch_bounds__(256)
void final_ln_kernel(const float* __restrict__ x, const float* __restrict__ b_out,
                     const float* __restrict__ g_o, const float* __restrict__ b_o,
                     float* __restrict__ y) {
    const float* z = (const float*)(g_pool + OFF_Z);
    int w = threadIdx.x >> 5, tx = threadIdx.x & 31;
    int r = blockIdx.x * 8 + w;
    int goff = row_goff(r);
    float v[8], s = 0.f, ss = 0.f;
    #pragma unroll
    for (int i = 0; i < 8; ++i) {
        int c = tx + 32 * i;
        v[i] = x[goff + c] + z[(size_t)r * 256 + c] + b_out[c];
        s += v[i]; ss += v[i] * v[i];
    }
    #pragma unroll
    for (int o = 16; o; o >>= 1) { s  += __shfl_xor_sync(0xffffffffu, s,  o);
                                   ss += __shfl_xor_sync(0xffffffffu, ss, o); }
    float mean = s * (1.f / 256.f);
    float inv  = rsqrtf(ss * (1.f / 256.f) - mean * mean + EPS);
    #pragma unroll
    for (int i = 0; i < 8; ++i) {
        int c = tx + 32 * i;
        y[goff + c] = (v[i] - mean) * inv * g_o[c] + b_o[c];
    }
}

extern "C" void kernel_launch(void* const* d_in, const int* in_sizes, int n_in,
                              void* d_out, int out_size) {
    (void)in_sizes; (void)n_in; (void)out_size;
    const float* x     = (const float*)d_in[0];
    const float* w_in  = (const float*)d_in[1];
    const float* b_in  = (const float*)d_in[2];
    const float* w_out = (const float*)d_in[3];
    const float* b_out = (const float*)d_in[4];
    const float* g_q   = (const float*)d_in[5];
    const float* b_q   = (const float*)d_in[6];
    const float* g_k   = (const float*)d_in[7];
    const float* b_k   = (const float*)d_in[8];
    const float* g_v   = (const float*)d_in[9];
    const float* b_v   = (const float*)d_in[10];
    const float* g_o   = (const float*)d_in[11];
    const float* b_o   = (const float*)d_in[12];
    float* y = (float*)d_out;

    cudaFuncSetAttribute(gemm_split_kernel, cudaFuncAttributeMaxDynamicSharedMemorySize, SMEM_GEMM);
    cudaFuncSetAttribute(attn_kernel, cudaFuncAttributeMaxDynamicSharedMemorySize, SMEM_ATTN);

    prep_w_kernel<<<768, 256>>>(w_in, b_in, g_q, b_q, g_k, b_k, g_v, b_v);
    prep_wo_kernel<<<256, 256>>>(w_out);
    ln_split_kernel<<<MT / 8, 256>>>(x);
    gemm_split_kernel<<<dim3(6, MT / 128), 256, SMEM_GEMM>>>(0);
    attn_kernel<<<2048, 256, SMEM_ATTN>>>();
    gemm_split_kernel<<<dim3(2, MT / 128), 256, SMEM_GEMM>>>(1);
    final_ln_kernel<<<MT / 8, 256>>>(x, b_out, g_o, b_o, y);
}

// round 16
// speedup vs baseline: 4.7335x; 1.0622x over previous
#include <cuda_runtime.h>
#include <cuda_fp16.h>
#include <math.h>
#include <stdint.h>

// WindowAttention: HMMA fp16 GEMMs + HMMA fp16 attention.
// B=32, 64x64, C=256, ws=8 -> MT=131072 token rows.
// R16: fused out-proj+residual+LN epilogue (z eliminated); 3-buffer GEMM0.

#define EPS 1e-5f
#define MT 131072

// scratch pool:
//  [0, 201M)      qkv fp16 [MT][768]
//  [402M, 469M)   xh fp16 [MT][256]  ; later o fp16
__device__ __align__(256) unsigned char g_pool[469762048ULL];
#define OFF_QKV 0ULL
#define OFF_XH  402653184ULL

__device__ __half g_wh[768 * 256];    // folded in_proj fp16 (row n, k-major)
__device__ float  g_bias[768];
__device__ __half g_woh[256 * 256];   // w_out fp16

typedef unsigned long long u64;
typedef unsigned int u32;

__device__ __forceinline__ uint32_t smem_u32(const void* p) {
    uint32_t a;
    asm("{ .reg .u64 t; cvta.to.shared.u64 t, %1; cvt.u32.u64 %0, t; }" : "=r"(a) : "l"(p));
    return a;
}
#define CP_COMMIT() asm volatile("cp.async.commit_group;" ::: "memory")
#define CP_WAIT(n)  asm volatile("cp.async.wait_group %0;" :: "n"(n) : "memory")

#define MMA16816(d, a, b) \
    asm volatile("mma.sync.aligned.m16n8k16.row.col.f32.f16.f16.f32 " \
        "{%0,%1,%2,%3}, {%4,%5,%6,%7}, {%8,%9}, {%0,%1,%2,%3};" \
        : "+f"((d)[0]), "+f"((d)[1]), "+f"((d)[2]), "+f"((d)[3]) \
        : "r"((a)[0]), "r"((a)[1]), "r"((a)[2]), "r"((a)[3]), \
          "r"((b)[0]), "r"((b)[1]))

#define LDM4(r, addr) \
    asm volatile("ldmatrix.sync.aligned.m8n8.x4.shared.b16 {%0,%1,%2,%3}, [%4];" \
        : "=r"((r)[0]), "=r"((r)[1]), "=r"((r)[2]), "=r"((r)[3]) : "r"(addr))

#define LDM4T(r, addr) \
    asm volatile("ldmatrix.sync.aligned.m8n8.x4.trans.shared.b16 {%0,%1,%2,%3}, [%4];" \
        : "=r"((r)[0]), "=r"((r)[1]), "=r"((r)[2]), "=r"((r)[3]) : "r"(addr))

__device__ __forceinline__ u32 h2u(float a, float b) {
    __half2 t = __floats2half2_rn(a, b);
    return *(u32*)&t;
}

__device__ __forceinline__ int row_goff(int r) {
    int win = r >> 6, t = r & 63;
    int b = win >> 6, wh8 = (win >> 3) & 7, ww = win & 7;
    return ((b * 64 + wh8 * 8 + (t >> 3)) * 64 + ww * 8 + (t & 7)) * 256;
}

// ---- prep: fold LN affine (+q scale) into in_proj fp16 ----
__global__ void prep_w_kernel(const float* __restrict__ w_in, const float* __restrict__ b_in,
                              const float* __restrict__ g_q, const float* __restrict__ b_q,
                              const float* __restrict__ g_k, const float* __restrict__ b_k,
                              const float* __restrict__ g_v, const float* __restrict__ b_v) {
    __shared__ float red[8];
    int col = blockIdx.x, k = threadIdx.x;
    const float* g; const float* b;
    if (col < 256)      { g = g_q; b = b_q; }
    else if (col < 512) { g = g_k; b = b_k; }
    else                { g = g_v; b = b_v; }
    const float f = (col < 256) ? 0.17677669529663689f : 1.0f;   // 1/sqrt(32)
    float w  = w_in[col * 256 + k];
    g_wh[col * 256 + k] = __float2half_rn(w * g[k] * f);
    float p = w * b[k];
    #pragma unroll
    for (int o = 16; o; o >>= 1) p += __shfl_xor_sync(0xffffffffu, p, o);
    if ((k & 31) == 0) red[k >> 5] = p;
    __syncthreads();
    if (k < 8) {
        float s = red[k];
        #pragma unroll
        for (int o = 4; o; o >>= 1) s += __shfl_xor_sync(0xffu, s, o);
        if (k == 0) g_bias[col] = (b_in[col] + s) * f;
    }
}

__global__ void prep_wo_kernel(const float* __restrict__ w_out) {
    int idx = blockIdx.x * 256 + threadIdx.x;
    g_woh[idx] = __float2half_rn(w_out[idx]);
}

// ---- LN + fp16 quantize ----
__global__ __launch_bounds__(256)
void ln_split_kernel(const float* __restrict__ x) {
    __half* xh = (__half*)(g_pool + OFF_XH);
    int w = threadIdx.x >> 5, tx = threadIdx.x & 31;
    int r = blockIdx.x * 8 + w;
    int goff = row_goff(r);
    float v[8], s = 0.f, ss = 0.f;
    #pragma unroll
    for (int i = 0; i < 8; ++i) { v[i] = x[goff + tx + 32 * i]; s += v[i]; ss += v[i] * v[i]; }
    #pragma unroll
    for (int o = 16; o; o >>= 1) { s  += __shfl_xor_sync(0xffffffffu, s,  o);
                                   ss += __shfl_xor_sync(0xffffffffu, ss, o); }
    float mean = s * (1.f / 256.f);
    float inv  = rsqrtf(ss * (1.f / 256.f) - mean * mean + EPS);
    #pragma unroll
    for (int i = 0; i < 8; ++i)
        xh[(size_t)r * 256 + tx + 32 * i] = __float2half_rn((v[i] - mean) * inv);
}

// ---- GEMM0: qkv(fp16) = xn@Win^T + bias. CTA 128x128, 3-buffer cp.async ----
static const int ROWH  = 72;
static const int ARR_H = 128 * ROWH;           // 9216 halves per array
static const int BUFB0 = 2 * ARR_H * 2;        // 36864 B (A+B)
static const int SMEM_G0 = 3 * BUFB0;          // 110592 B

__global__ __launch_bounds__(256, 2)
void gemm0_kernel() {
    extern __shared__ __half smh[];
    const int tid = threadIdx.x, wid = tid >> 5, lane = tid & 31;
    const int gid = lane >> 2, tig = lane & 3;
    const int mw = wid >> 2, nw = wid & 3;
    const int nt = blockIdx.x, mt = blockIdx.y;

    const __half* Asrc = (const __half*)(g_pool + OFF_XH) + (size_t)(mt * 128) * 256;
    const __half* Bsrc = g_wh + (size_t)(nt * 128) * 256;

    const __half* psrc[8]; u32 pdst[8];
    const u32 sbm = smem_u32(smh);
    #pragma unroll
    for (int t = 0; t < 8; ++t) {
        int idx = tid + t * 256, arr = idx >> 10, e = idx & 1023, row = e >> 3, seg = e & 7;
        psrc[t] = (arr ? Bsrc : Asrc) + row * 256 + seg * 8;
        pdst[t] = sbm + (u32)((arr * ARR_H + row * ROWH + seg * 8) * 2);
    }

    float acc[4][4][4];
    #pragma unroll
    for (int m = 0; m < 4; ++m)
        #pragma unroll
        for (int n = 0; n < 4; ++n)
            #pragma unroll
            for (int q = 0; q < 4; ++q) acc[m][n][q] = 0.f;

    const int lr = lane & 15, lk = lane >> 4;
    const u32 aoff = (u32)(((mw * 64 + lr) * ROWH + lk * 8) * 2);
    const u32 boff = (u32)(ARR_H * 2 + ((nw * 32 + lr) * ROWH + lk * 8) * 2);

    // prologue: chunks 0,1 into buffers 0,1
    #pragma unroll
    for (int c = 0; c < 2; ++c) {
        const u32 bo = (u32)(c * BUFB0);
        #pragma unroll
        for (int t = 0; t < 8; ++t) {
            asm volatile("cp.async.cg.shared.global [%0], [%1], 16;"
                         :: "r"(pdst[t] + bo), "l"(psrc[t]) : "memory");
            psrc[t] += 64;
        }
        CP_COMMIT();
    }

    #pragma unroll
    for (int kc = 0; kc < 4; ++kc) {
        CP_WAIT(1);
        __syncthreads();
        if (kc < 2) {
            const u32 bo = (u32)(((kc + 2) % 3) * BUFB0);
            #pragma unroll
            for (int t = 0; t < 8; ++t) {
                asm volatile("cp.async.cg.shared.global [%0], [%1], 16;"
                             :: "r"(pdst[t] + bo), "l"(psrc[t]) : "memory");
                psrc[t] += 64;
            }
        }
        CP_COMMIT();
        const u32 base = sbm + (u32)((kc % 3) * BUFB0);
        #pragma unroll
        for (int ks = 0; ks < 4; ++ks) {
            const u32 kb = (u32)(ks * 32);
            u32 A_[4][4], B_[2][4];
            #pragma unroll
            for (int m = 0; m < 4; ++m)
                LDM4(A_[m], base + aoff + m * (16 * ROWH * 2) + kb);
            #pragma unroll
            for (int p = 0; p < 2; ++p)
                LDM4(B_[p], base + boff + p * (16 * ROWH * 2) + kb);
            #pragma unroll
            for (int m = 0; m < 4; ++m)
                #pragma unroll
                for (int p = 0; p < 2; ++p)
                    #pragma unroll
                    for (int sub = 0; sub < 2; ++sub) {
                        u32 b2[2] = { B_[p][sub], B_[p][sub + 2] };
                        MMA16816(acc[m][p * 2 + sub], A_[m], b2);
                    }
        }
    }

    __half* out = (__half*)(g_pool + OFF_QKV);
    #pragma unroll
    for (int m = 0; m < 4; ++m) {
        int row = mt * 128 + mw * 64 + m * 16 + gid;
        #pragma unroll
        for (int n = 0; n < 4; ++n) {
            int col = nt * 128 + nw * 32 + n * 8 + tig * 2;
            float b0 = g_bias[col], b1 = g_bias[col + 1];
            *(u32*)(out + (size_t)row * 768 + col) =
                h2u(acc[m][n][0] + b0, acc[m][n][1] + b1);
            *(u32*)(out + (size_t)(row + 8) * 768 + col) =
                h2u(acc[m][n][2] + b0, acc[m][n][3] + b1);
        }
    }
}

// ---- attention: CTA = window, 8 warps = 8 heads, HMMA fp16 ----
static const int SMEM_ATTN = 64 * 776 * 2;

__global__ __launch_bounds__(256, 2)
void attn_kernel() {
    extern __shared__ __half sk[];
    const __half* qkv = (const __half*)(g_pool + OFF_QKV);
    __half* o = (__half*)(g_pool + OFF_XH);

    const int tid = threadIdx.x, wid = tid >> 5, lane = tid & 31;
    const int gid = lane >> 2, tig = lane & 3;
    const int R = blockIdx.x * 64;

    {
        const uint4* src = (const uint4*)(qkv + (size_t)R * 768);
        for (int i = tid; i < 6144; i += 256) {
            int r = i / 96, c = i % 96;
            *(uint4*)(sk + r * 776 + c * 8) = src[(size_t)r * 96 + c];
        }
    }
    __syncthreads();

    const int h = wid;
    const u32 sb = smem_u32(sk);
    const int lr = lane & 15, lk = lane >> 4;
    const u32 qaddr = sb + (u32)((lr * 776 + h * 32 + lk * 8) * 2);
    const u32 kaddr = sb + (u32)((lr * 776 + 256 + h * 32 + lk * 8) * 2);
    const u32 vaddr = sb + (u32)((((lane & 7) + ((lane >> 3) & 1) * 8) * 776
                                  + 512 + h * 32 + (lane >> 4) * 8) * 2);

    u32 rv[4][2][4];
    #pragma unroll
    for (int t = 0; t < 4; ++t)
        #pragma unroll
        for (int g = 0; g < 2; ++g)
            LDM4T(rv[t][g], vaddr + (u32)((t * 16 * 776 + g * 16) * 2));

    const u32 ROW16 = (u32)(16 * 776 * 2);

    for (int m = 0; m < 4; ++m) {
        u32 QA[2][4];
        LDM4(QA[0], qaddr + m * ROW16);
        LDM4(QA[1], qaddr + m * ROW16 + 32);

        float S[8][4];
        #pragma unroll
        for (int n = 0; n < 8; ++n)
            #pragma unroll
            for (int q = 0; q < 4; ++q) S[n][q] = 0.f;
        #pragma unroll
        for (int p = 0; p < 4; ++p) {
            u32 kb0[4], kb1[4];
            LDM4(kb0, kaddr + p * ROW16);
            LDM4(kb1, kaddr + p * ROW16 + 32);
            #pragma unroll
            for (int sub = 0; sub < 2; ++sub) {
                u32 p0[2] = { kb0[sub], kb0[sub + 2] };
                u32 p1[2] = { kb1[sub], kb1[sub + 2] };
                MMA16816(S[p * 2 + sub], QA[0], p0);
                MMA16816(S[p * 2 + sub], QA[1], p1);
            }
        }

        float inv0, inv1;
        {
            float mx0 = -1e30f, mx1 = -1e30f;
            #pragma unroll
            for (int n = 0; n < 8; ++n) {
                mx0 = fmaxf(mx0, fmaxf(S[n][0], S[n][1]));
                mx1 = fmaxf(mx1, fmaxf(S[n][2], S[n][3]));
            }
            #pragma unroll
            for (int d = 1; d <= 2; d <<= 1) {
                mx0 = fmaxf(mx0, __shfl_xor_sync(0xffffffffu, mx0, d));
                mx1 = fmaxf(mx1, __shfl_xor_sync(0xffffffffu, mx1, d));
            }
            float s0 = 0.f, s1 = 0.f;
            #pragma unroll
            for (int n = 0; n < 8; ++n) {
                S[n][0] = __expf(S[n][0] - mx0); s0 += S[n][0];
                S[n][1] = __expf(S[n][1] - mx0); s0 += S[n][1];
                S[n][2] = __expf(S[n][2] - mx1); s1 += S[n][2];
                S[n][3] = __expf(S[n][3] - mx1); s1 += S[n][3];
            }
            #pragma unroll
            for (int d = 1; d <= 2; d <<= 1) {
                s0 += __shfl_xor_sync(0xffffffffu, s0, d);
                s1 += __shfl_xor_sync(0xffffffffu, s1, d);
            }
            inv0 = 1.f / s0; inv1 = 1.f / s1;
        }

        float O[4][4];
        #pragma unroll
        for (int n = 0; n < 4; ++n)
            #pragma unroll
            for (int q = 0; q < 4; ++q) O[n][q] = 0.f;
        #pragma unroll
        for (int t = 0; t < 4; ++t) {
            u32 PA[4];
            PA[0] = h2u(S[2 * t][0],     S[2 * t][1]);
            PA[1] = h2u(S[2 * t][2],     S[2 * t][3]);
            PA[2] = h2u(S[2 * t + 1][0], S[2 * t + 1][1]);
            PA[3] = h2u(S[2 * t + 1][2], S[2 * t + 1][3]);
            #pragma unroll
            for (int n = 0; n < 4; ++n) {
                u32 vp[2] = { rv[t][n >> 1][(n & 1) * 2], rv[t][n >> 1][(n & 1) * 2 + 1] };
                MMA16816(O[n], PA, vp);
            }
        }

        int row0 = R + m * 16 + gid;
        #pragma unroll
        for (int n = 0; n < 4; ++n) {
            int col = h * 32 + n * 8 + tig * 2;
            *(u32*)(o + (size_t)row0 * 256 + col) = h2u(O[n][0] * inv0, O[n][1] * inv0);
            *(u32*)(o + (size_t)(row0 + 8) * 256 + col) = h2u(O[n][2] * inv1, O[n][3] * inv1);
        }
    }
}

// ---- GEMM1 fused: y = LN(x + o@Wout^T + b_out) * g_o + b_o ----
// CTA = 64 rows x 256 cols. 8 warps (mw 0-1, nw 0-3), warp tile 32x64.
static const int G1_AH  = 64 * ROWH;            // 4608 halves
static const int G1_BH  = 256 * ROWH;           // 18432 halves
static const int G1_BUF = (G1_AH + G1_BH) * 2;  // 46080 B
static const int SMEM_G1 = 2 * G1_BUF;          // 92160 B

__global__ __launch_bounds__(256, 2)
void gemm1_fused_kernel(const float* __restrict__ x, const float* __restrict__ b_out,
                        const float* __restrict__ g_o, const float* __restrict__ b_o,
                        float* __restrict__ y) {
    extern __shared__ __half smh[];
    const int tid = threadIdx.x, wid = tid >> 5, lane = tid & 31;
    const int gid = lane >> 2, tig = lane & 3;
    const int mw = wid >> 2, nw = wid & 3;
    const int R = blockIdx.x * 64;

    const __half* Asrc = (const __half*)(g_pool + OFF_XH) + (size_t)R * 256;
    const u32 sbm = smem_u32(smh);

    float acc[2][8][4];
    #pragma unroll
    for (int m = 0; m < 2; ++m)
        #pragma unroll
        for (int n = 0; n < 8; ++n)
            #pragma unroll
            for (int q = 0; q < 4; ++q) acc[m][n][q] = 0.f;

    const int lr = lane & 15, lk = lane >> 4;
    const u32 aoff = (u32)(((mw * 32 + lr) * ROWH + lk * 8) * 2);
    const u32 boff = (u32)(G1_AH * 2 + ((nw * 64 + lr) * ROWH + lk * 8) * 2);

    // prefetch helper (recomputed addressing, 10 x 16B per thread)
    const int arow = tid >> 3, aseg = tid & 7;          // t=0,1: A rows 0..63
    #define G1_PF(kc, bo) do { \
        if (arow + 32 * 0 < 64) {} \
        asm volatile("cp.async.cg.shared.global [%0], [%1], 16;" \
            :: "r"(sbm + (bo) + (u32)(((arow) * ROWH + aseg * 8) * 2)), \
               "l"(Asrc + (arow) * 256 + (kc) * 64 + aseg * 8) : "memory"); \
        asm volatile("cp.async.cg.shared.global [%0], [%1], 16;" \
            :: "r"(sbm + (bo) + (u32)(((arow + 32) * ROWH + aseg * 8) * 2)), \
               "l"(Asrc + (arow + 32) * 256 + (kc) * 64 + aseg * 8) : "memory"); \
        _Pragma("unroll") \
        for (int t = 0; t < 8; ++t) { \
            int brow = t * 32 + (tid >> 3); \
            asm volatile("cp.async.cg.shared.global [%0], [%1], 16;" \
                :: "r"(sbm + (bo) + (u32)((G1_AH + brow * ROWH + aseg * 8) * 2)), \
                   "l"(g_woh + (size_t)brow * 256 + (kc) * 64 + aseg * 8) : "memory"); \
        } \
    } while (0)

    G1_PF(0, 0u);
    CP_COMMIT();

    for (int kc = 0; kc < 4; ++kc) {
        if (kc < 3) { G1_PF(kc + 1, (u32)(((kc + 1) & 1) * G1_BUF)); }
        CP_COMMIT();
        CP_WAIT(1);
        __syncthreads();
        const u32 base = sbm + (u32)((kc & 1) * G1_BUF);
        #pragma unroll
        for (int ks = 0; ks < 4; ++ks) {
            const u32 kb = (u32)(ks * 32);
            u32 A_[2][4], B_[4][4];
            #pragma unroll
            for (int m = 0; m < 2; ++m)
                LDM4(A_[m], base + aoff + m * (16 * ROWH * 2) + kb);
            #pragma unroll
            for (int p = 0; p < 4; ++p)
                LDM4(B_[p], base + boff + p * (16 * ROWH * 2) + kb);
            #pragma unroll
            for (int m = 0; m < 2; ++m)
                #pragma unroll
                for (int p = 0; p < 4; ++p)
                    #pragma unroll
                    for (int sub = 0; sub < 2; ++sub) {
                        u32 b2[2] = { B_[p][sub], B_[p][sub + 2] };
                        MMA16816(acc[m][p * 2 + sub], A_[m], b2);
                    }
        }
        __syncthreads();
    }

    // stage acc to smem fp32 [64][260]
    float* stage = (float*)smh;
    #pragma unroll
    for (int m = 0; m < 2; ++m) {
        int row = mw * 32 + m * 16 + gid;
        #pragma unroll
        for (int n = 0; n < 8; ++n) {
            int col = nw * 64 + n * 8 + tig * 2;
            *(float2*)(stage + row * 260 + col) = make_float2(acc[m][n][0], acc[m][n][1]);
            *(float2*)(stage + (row + 8) * 260 + col) = make_float2(acc[m][n][2], acc[m][n][3]);
        }
    }
    __syncthreads();

    // warp wid: rows wid*8 .. +7 -> residual + LN + store
    const int tx = lane;
    for (int i = 0; i < 8; ++i) {
        int r = wid * 8 + i;
        int goff = row_goff(R + r);
        float v[8], s = 0.f, ss = 0.f;
        #pragma unroll
        for (int j = 0; j < 8; ++j) {
            int c = tx + 32 * j;
            v[j] = stage[r * 260 + c] + x[goff + c] + b_out[c];
            s += v[j]; ss += v[j] * v[j];
        }
        #pragma unroll
        for (int o = 16; o; o >>= 1) { s  += __shfl_xor_sync(0xffffffffu, s,  o);
                                       ss += __shfl_xor_sync(0xffffffffu, ss, o); }
        float mean = s * (1.f / 256.f);
        float inv  = rsqrtf(ss * (1.f / 256.f) - mean * mean + EPS);
        #pragma unroll
        for (int j = 0; j < 8; ++j) {
            int c = tx + 32 * j;
            y[goff + c] = (v[j] - mean) * inv * g_o[c] + b_o[c];
        }
    }
}

extern "C" void kernel_launch(void* const* d_in, const int* in_sizes, int n_in,
                              void* d_out, int out_size) {
    (void)in_sizes; (void)n_in; (void)out_size;
    const float* x     = (const float*)d_in[0];
    const float* w_in  = (const float*)d_in[1];
    const float* b_in  = (const float*)d_in[2];
    const float* w_out = (const float*)d_in[3];
    const float* b_out = (const float*)d_in[4];
    const float* g_q   = (const float*)d_in[5];
    const float* b_q   = (const float*)d_in[6];
    const float* g_k   = (const float*)d_in[7];
    const float* b_k   = (const float*)d_in[8];
    const float* g_v   = (const float*)d_in[9];
    const float* b_v   = (const float*)d_in[10];
    const float* g_o   = (const float*)d_in[11];
    const float* b_o   = (const float*)d_in[12];
    float* y = (float*)d_out;

    cudaFuncSetAttribute(gemm0_kernel, cudaFuncAttributeMaxDynamicSharedMemorySize, SMEM_G0);
    cudaFuncSetAttribute(attn_kernel, cudaFuncAttributeMaxDynamicSharedMemorySize, SMEM_ATTN);
    cudaFuncSetAttribute(gemm1_fused_kernel, cudaFuncAttributeMaxDynamicSharedMemorySize, SMEM_G1);

    prep_w_kernel<<<768, 256>>>(w_in, b_in, g_q, b_q, g_k, b_k, g_v, b_v);
    prep_wo_kernel<<<256, 256>>>(w_out);
    ln_split_kernel<<<MT / 8, 256>>>(x);
    gemm0_kernel<<<dim3(6, MT / 128), 256, SMEM_G0>>>();
    attn_kernel<<<2048, 256, SMEM_ATTN>>>();
    gemm1_fused_kernel<<<MT / 64, 256, SMEM_G1>>>(x, b_out, g_o, b_o, y);
}

// round 17
// speedup vs baseline: 5.0171x; 1.0599x over previous
#include <cuda_runtime.h>
#include <cuda_fp16.h>
#include <math.h>
#include <stdint.h>

// WindowAttention: HMMA fp16 GEMMs + HMMA fp16 attention.
// B=32, 64x64, C=256, ws=8 -> MT=131072 token rows.
// R17: coalesced staged epilogues (GEMM0 + attn), bias in acc-init.

#define EPS 1e-5f
#define MT 131072

// scratch pool:
//  [0, 201M)      qkv fp16 [MT][768]
//  [402M, 469M)   xh fp16 [MT][256]  ; later o fp16
__device__ __align__(256) unsigned char g_pool[469762048ULL];
#define OFF_QKV 0ULL
#define OFF_XH  402653184ULL

__device__ __half g_wh[768 * 256];    // folded in_proj fp16 (row n, k-major)
__device__ float  g_bias[768];
__device__ __half g_woh[256 * 256];   // w_out fp16

typedef unsigned long long u64;
typedef unsigned int u32;

__device__ __forceinline__ uint32_t smem_u32(const void* p) {
    uint32_t a;
    asm("{ .reg .u64 t; cvta.to.shared.u64 t, %1; cvt.u32.u64 %0, t; }" : "=r"(a) : "l"(p));
    return a;
}
#define CP_COMMIT() asm volatile("cp.async.commit_group;" ::: "memory")
#define CP_WAIT(n)  asm volatile("cp.async.wait_group %0;" :: "n"(n) : "memory")

#define MMA16816(d, a, b) \
    asm volatile("mma.sync.aligned.m16n8k16.row.col.f32.f16.f16.f32 " \
        "{%0,%1,%2,%3}, {%4,%5,%6,%7}, {%8,%9}, {%0,%1,%2,%3};" \
        : "+f"((d)[0]), "+f"((d)[1]), "+f"((d)[2]), "+f"((d)[3]) \
        : "r"((a)[0]), "r"((a)[1]), "r"((a)[2]), "r"((a)[3]), \
          "r"((b)[0]), "r"((b)[1]))

#define LDM4(r, addr) \
    asm volatile("ldmatrix.sync.aligned.m8n8.x4.shared.b16 {%0,%1,%2,%3}, [%4];" \
        : "=r"((r)[0]), "=r"((r)[1]), "=r"((r)[2]), "=r"((r)[3]) : "r"(addr))

#define LDM4T(r, addr) \
    asm volatile("ldmatrix.sync.aligned.m8n8.x4.trans.shared.b16 {%0,%1,%2,%3}, [%4];" \
        : "=r"((r)[0]), "=r"((r)[1]), "=r"((r)[2]), "=r"((r)[3]) : "r"(addr))

__device__ __forceinline__ u32 h2u(float a, float b) {
    __half2 t = __floats2half2_rn(a, b);
    return *(u32*)&t;
}

__device__ __forceinline__ int row_goff(int r) {
    int win = r >> 6, t = r & 63;
    int b = win >> 6, wh8 = (win >> 3) & 7, ww = win & 7;
    return ((b * 64 + wh8 * 8 + (t >> 3)) * 64 + ww * 8 + (t & 7)) * 256;
}

// ---- prep: fold LN affine (+q scale) into in_proj fp16 ----
__global__ void prep_w_kernel(const float* __restrict__ w_in, const float* __restrict__ b_in,
                              const float* __restrict__ g_q, const float* __restrict__ b_q,
                              const float* __restrict__ g_k, const float* __restrict__ b_k,
                              const float* __restrict__ g_v, const float* __restrict__ b_v) {
    __shared__ float red[8];
    int col = blockIdx.x, k = threadIdx.x;
    const float* g; const float* b;
    if (col < 256)      { g = g_q; b = b_q; }
    else if (col < 512) { g = g_k; b = b_k; }
    else                { g = g_v; b = b_v; }
    const float f = (col < 256) ? 0.17677669529663689f : 1.0f;   // 1/sqrt(32)
    float w  = w_in[col * 256 + k];
    g_wh[col * 256 + k] = __float2half_rn(w * g[k] * f);
    float p = w * b[k];
    #pragma unroll
    for (int o = 16; o; o >>= 1) p += __shfl_xor_sync(0xffffffffu, p, o);
    if ((k & 31) == 0) red[k >> 5] = p;
    __syncthreads();
    if (k < 8) {
        float s = red[k];
        #pragma unroll
        for (int o = 4; o; o >>= 1) s += __shfl_xor_sync(0xffu, s, o);
        if (k == 0) g_bias[col] = (b_in[col] + s) * f;
    }
}

__global__ void prep_wo_kernel(const float* __restrict__ w_out) {
    int idx = blockIdx.x * 256 + threadIdx.x;
    g_woh[idx] = __float2half_rn(w_out[idx]);
}

// ---- LN + fp16 quantize ----
__global__ __launch_bounds__(256)
void ln_split_kernel(const float* __restrict__ x) {
    __half* xh = (__half*)(g_pool + OFF_XH);
    int w = threadIdx.x >> 5, tx = threadIdx.x & 31;
    int r = blockIdx.x * 8 + w;
    int goff = row_goff(r);
    float v[8], s = 0.f, ss = 0.f;
    #pragma unroll
    for (int i = 0; i < 8; ++i) { v[i] = x[goff + tx + 32 * i]; s += v[i]; ss += v[i] * v[i]; }
    #pragma unroll
    for (int o = 16; o; o >>= 1) { s  += __shfl_xor_sync(0xffffffffu, s,  o);
                                   ss += __shfl_xor_sync(0xffffffffu, ss, o); }
    float mean = s * (1.f / 256.f);
    float inv  = rsqrtf(ss * (1.f / 256.f) - mean * mean + EPS);
    #pragma unroll
    for (int i = 0; i < 8; ++i)
        xh[(size_t)r * 256 + tx + 32 * i] = __float2half_rn((v[i] - mean) * inv);
}

// ---- GEMM0: qkv(fp16) = xn@Win^T + bias. CTA 128x128, 3-buffer cp.async ----
static const int ROWH  = 72;
static const int ARR_H = 128 * ROWH;           // 9216 halves per array
static const int BUFB0 = 2 * ARR_H * 2;        // 36864 B (A+B)
static const int SMEM_G0 = 3 * BUFB0;          // 110592 B

__global__ __launch_bounds__(256, 2)
void gemm0_kernel() {
    extern __shared__ __half smh[];
    const int tid = threadIdx.x, wid = tid >> 5, lane = tid & 31;
    const int gid = lane >> 2, tig = lane & 3;
    const int mw = wid >> 2, nw = wid & 3;
    const int nt = blockIdx.x, mt = blockIdx.y;

    const __half* Asrc = (const __half*)(g_pool + OFF_XH) + (size_t)(mt * 128) * 256;
    const __half* Bsrc = g_wh + (size_t)(nt * 128) * 256;

    const __half* psrc[8]; u32 pdst[8];
    const u32 sbm = smem_u32(smh);
    #pragma unroll
    for (int t = 0; t < 8; ++t) {
        int idx = tid + t * 256, arr = idx >> 10, e = idx & 1023, row = e >> 3, seg = e & 7;
        psrc[t] = (arr ? Bsrc : Asrc) + row * 256 + seg * 8;
        pdst[t] = sbm + (u32)((arr * ARR_H + row * ROWH + seg * 8) * 2);
    }

    // bias folded into accumulator init (MMA C-operand)
    float acc[4][4][4];
    {
        float bi[4][2];
        #pragma unroll
        for (int n = 0; n < 4; ++n) {
            int col = nt * 128 + nw * 32 + n * 8 + tig * 2;
            bi[n][0] = g_bias[col]; bi[n][1] = g_bias[col + 1];
        }
        #pragma unroll
        for (int m = 0; m < 4; ++m)
            #pragma unroll
            for (int n = 0; n < 4; ++n) {
                acc[m][n][0] = bi[n][0]; acc[m][n][1] = bi[n][1];
                acc[m][n][2] = bi[n][0]; acc[m][n][3] = bi[n][1];
            }
    }

    const int lr = lane & 15, lk = lane >> 4;
    const u32 aoff = (u32)(((mw * 64 + lr) * ROWH + lk * 8) * 2);
    const u32 boff = (u32)(ARR_H * 2 + ((nw * 32 + lr) * ROWH + lk * 8) * 2);

    // prologue: chunks 0,1 into buffers 0,1
    #pragma unroll
    for (int c = 0; c < 2; ++c) {
        const u32 bo = (u32)(c * BUFB0);
        #pragma unroll
        for (int t = 0; t < 8; ++t) {
            asm volatile("cp.async.cg.shared.global [%0], [%1], 16;"
                         :: "r"(pdst[t] + bo), "l"(psrc[t]) : "memory");
            psrc[t] += 64;
        }
        CP_COMMIT();
    }

    #pragma unroll
    for (int kc = 0; kc < 4; ++kc) {
        CP_WAIT(1);
        __syncthreads();
        if (kc < 2) {
            const u32 bo = (u32)(((kc + 2) % 3) * BUFB0);
            #pragma unroll
            for (int t = 0; t < 8; ++t) {
                asm volatile("cp.async.cg.shared.global [%0], [%1], 16;"
                             :: "r"(pdst[t] + bo), "l"(psrc[t]) : "memory");
                psrc[t] += 64;
            }
        }
        CP_COMMIT();
        const u32 base = sbm + (u32)((kc % 3) * BUFB0);
        #pragma unroll
        for (int ks = 0; ks < 4; ++ks) {
            const u32 kb = (u32)(ks * 32);
            u32 A_[4][4], B_[2][4];
            #pragma unroll
            for (int m = 0; m < 4; ++m)
                LDM4(A_[m], base + aoff + m * (16 * ROWH * 2) + kb);
            #pragma unroll
            for (int p = 0; p < 2; ++p)
                LDM4(B_[p], base + boff + p * (16 * ROWH * 2) + kb);
            #pragma unroll
            for (int m = 0; m < 4; ++m)
                #pragma unroll
                for (int p = 0; p < 2; ++p)
                    #pragma unroll
                    for (int sub = 0; sub < 2; ++sub) {
                        u32 b2[2] = { B_[p][sub], B_[p][sub + 2] };
                        MMA16816(acc[m][p * 2 + sub], A_[m], b2);
                    }
        }
    }

    // staged coalesced epilogue: acc -> smem fp16 [128][136] -> uint4 stores
    __syncthreads();
    {
        __half* stg = smh;
        #pragma unroll
        for (int m = 0; m < 4; ++m) {
            int row = mw * 64 + m * 16 + gid;
            #pragma unroll
            for (int n = 0; n < 4; ++n) {
                int col = nw * 32 + n * 8 + tig * 2;
                *(u32*)(stg + row * 136 + col)       = h2u(acc[m][n][0], acc[m][n][1]);
                *(u32*)(stg + (row + 8) * 136 + col) = h2u(acc[m][n][2], acc[m][n][3]);
            }
        }
    }
    __syncthreads();
    {
        __half* out = (__half*)(g_pool + OFF_QKV) + (size_t)(mt * 128) * 768 + nt * 128;
        const __half* stg = smh;
        #pragma unroll
        for (int t = 0; t < 8; ++t) {
            int i = tid + t * 256;            // 2048 uint4s
            int row = i >> 4, seg = i & 15;
            *(uint4*)(out + (size_t)row * 768 + seg * 8) =
                *(const uint4*)(stg + row * 136 + seg * 8);
        }
    }
}

// ---- attention: CTA = window, 8 warps = 8 heads, HMMA fp16 ----
static const int SMEM_ATTN = 64 * 776 * 2;

__global__ __launch_bounds__(256, 2)
void attn_kernel() {
    extern __shared__ __half sk[];
    const __half* qkv = (const __half*)(g_pool + OFF_QKV);
    __half* o = (__half*)(g_pool + OFF_XH);

    const int tid = threadIdx.x, wid = tid >> 5, lane = tid & 31;
    const int gid = lane >> 2, tig = lane & 3;
    const int R = blockIdx.x * 64;

    {
        const uint4* src = (const uint4*)(qkv + (size_t)R * 768);
        for (int i = tid; i < 6144; i += 256) {
            int r = i / 96, c = i % 96;
            *(uint4*)(sk + r * 776 + c * 8) = src[(size_t)r * 96 + c];
        }
    }
    __syncthreads();

    const int h = wid;
    const u32 sb = smem_u32(sk);
    const int lr = lane & 15, lk = lane >> 4;
    const u32 qaddr = sb + (u32)((lr * 776 + h * 32 + lk * 8) * 2);
    const u32 kaddr = sb + (u32)((lr * 776 + 256 + h * 32 + lk * 8) * 2);
    const u32 vaddr = sb + (u32)((((lane & 7) + ((lane >> 3) & 1) * 8) * 776
                                  + 512 + h * 32 + (lane >> 4) * 8) * 2);

    u32 rv[4][2][4];
    #pragma unroll
    for (int t = 0; t < 4; ++t)
        #pragma unroll
        for (int g = 0; g < 2; ++g)
            LDM4T(rv[t][g], vaddr + (u32)((t * 16 * 776 + g * 16) * 2));

    const u32 ROW16 = (u32)(16 * 776 * 2);

    float Ofin[4][4][4];   // per m-tile outputs kept for staged store

    for (int m = 0; m < 4; ++m) {
        u32 QA[2][4];
        LDM4(QA[0], qaddr + m * ROW16);
        LDM4(QA[1], qaddr + m * ROW16 + 32);

        float S[8][4];
        #pragma unroll
        for (int n = 0; n < 8; ++n)
            #pragma unroll
            for (int q = 0; q < 4; ++q) S[n][q] = 0.f;
        #pragma unroll
        for (int p = 0; p < 4; ++p) {
            u32 kb0[4], kb1[4];
            LDM4(kb0, kaddr + p * ROW16);
            LDM4(kb1, kaddr + p * ROW16 + 32);
            #pragma unroll
            for (int sub = 0; sub < 2; ++sub) {
                u32 p0[2] = { kb0[sub], kb0[sub + 2] };
                u32 p1[2] = { kb1[sub], kb1[sub + 2] };
                MMA16816(S[p * 2 + sub], QA[0], p0);
                MMA16816(S[p * 2 + sub], QA[1], p1);
            }
        }

        float inv0, inv1;
        {
            float mx0 = -1e30f, mx1 = -1e30f;
            #pragma unroll
            for (int n = 0; n < 8; ++n) {
                mx0 = fmaxf(mx0, fmaxf(S[n][0], S[n][1]));
                mx1 = fmaxf(mx1, fmaxf(S[n][2], S[n][3]));
            }
            #pragma unroll
            for (int d = 1; d <= 2; d <<= 1) {
                mx0 = fmaxf(mx0, __shfl_xor_sync(0xffffffffu, mx0, d));
                mx1 = fmaxf(mx1, __shfl_xor_sync(0xffffffffu, mx1, d));
            }
            float s0 = 0.f, s1 = 0.f;
            #pragma unroll
            for (int n = 0; n < 8; ++n) {
                S[n][0] = __expf(S[n][0] - mx0); s0 += S[n][0];
                S[n][1] = __expf(S[n][1] - mx0); s0 += S[n][1];
                S[n][2] = __expf(S[n][2] - mx1); s1 += S[n][2];
                S[n][3] = __expf(S[n][3] - mx1); s1 += S[n][3];
            }
            #pragma unroll
            for (int d = 1; d <= 2; d <<= 1) {
                s0 += __shfl_xor_sync(0xffffffffu, s0, d);
                s1 += __shfl_xor_sync(0xffffffffu, s1, d);
            }
            inv0 = 1.f / s0; inv1 = 1.f / s1;
        }

        float O[4][4];
        #pragma unroll
        for (int n = 0; n < 4; ++n)
            #pragma unroll
            for (int q = 0; q < 4; ++q) O[n][q] = 0.f;
        #pragma unroll
        for (int t = 0; t < 4; ++t) {
            u32 PA[4];
            PA[0] = h2u(S[2 * t][0],     S[2 * t][1]);
            PA[1] = h2u(S[2 * t][2],     S[2 * t][3]);
            PA[2] = h2u(S[2 * t + 1][0], S[2 * t + 1][1]);
            PA[3] = h2u(S[2 * t + 1][2], S[2 * t + 1][3]);
            #pragma unroll
            for (int n = 0; n < 4; ++n) {
                u32 vp[2] = { rv[t][n >> 1][(n & 1) * 2], rv[t][n >> 1][(n & 1) * 2 + 1] };
                MMA16816(O[n], PA, vp);
            }
        }
        #pragma unroll
        for (int n = 0; n < 4; ++n) {
            Ofin[m][n][0] = O[n][0] * inv0; Ofin[m][n][1] = O[n][1] * inv0;
            Ofin[m][n][2] = O[n][2] * inv1; Ofin[m][n][3] = O[n][3] * inv1;
        }
    }

    // staged coalesced store: o window [64][264] fp16 in smem -> uint4 rows
    __syncthreads();
    {
        __half* stg = sk;
        #pragma unroll
        for (int m = 0; m < 4; ++m) {
            int row = m * 16 + gid;
            #pragma unroll
            for (int n = 0; n < 4; ++n) {
                int col = h * 32 + n * 8 + tig * 2;
                *(u32*)(stg + row * 264 + col)       = h2u(Ofin[m][n][0], Ofin[m][n][1]);
                *(u32*)(stg + (row + 8) * 264 + col) = h2u(Ofin[m][n][2], Ofin[m][n][3]);
            }
        }
    }
    __syncthreads();
    {
        __half* dst = o + (size_t)R * 256;
        const __half* stg = sk;
        #pragma unroll
        for (int t = 0; t < 8; ++t) {
            int i = tid + t * 256;            // 2048 uint4s
            int row = i >> 5, seg = i & 31;
            *(uint4*)(dst + (size_t)row * 256 + seg * 8) =
                *(const uint4*)(stg + row * 264 + seg * 8);
        }
    }
}

// ---- GEMM1 fused: y = LN(x + o@Wout^T + b_out) * g_o + b_o ----
static const int G1_AH  = 64 * ROWH;            // 4608 halves
static const int G1_BH  = 256 * ROWH;           // 18432 halves
static const int G1_BUF = (G1_AH + G1_BH) * 2;  // 46080 B
static const int SMEM_G1 = 2 * G1_BUF;          // 92160 B

__global__ __launch_bounds__(256, 2)
void gemm1_fused_kernel(const float* __restrict__ x, const float* __restrict__ b_out,
                        const float* __restrict__ g_o, const float* __restrict__ b_o,
                        float* __restrict__ y) {
    extern __shared__ __half smh[];
    const int tid = threadIdx.x, wid = tid >> 5, lane = tid & 31;
    const int gid = lane >> 2, tig = lane & 3;
    const int mw = wid >> 2, nw = wid & 3;
    const int R = blockIdx.x * 64;

    const __half* Asrc = (const __half*)(g_pool + OFF_XH) + (size_t)R * 256;
    const u32 sbm = smem_u32(smh);

    float acc[2][8][4];
    #pragma unroll
    for (int m = 0; m < 2; ++m)
        #pragma unroll
        for (int n = 0; n < 8; ++n)
            #pragma unroll
            for (int q = 0; q < 4; ++q) acc[m][n][q] = 0.f;

    const int lr = lane & 15, lk = lane >> 4;
    const u32 aoff = (u32)(((mw * 32 + lr) * ROWH + lk * 8) * 2);
    const u32 boff = (u32)(G1_AH * 2 + ((nw * 64 + lr) * ROWH + lk * 8) * 2);

    const int arow = tid >> 3, aseg = tid & 7;
    #define G1_PF(kc, bo) do { \
        asm volatile("cp.async.cg.shared.global [%0], [%1], 16;" \
            :: "r"(sbm + (bo) + (u32)(((arow) * ROWH + aseg * 8) * 2)), \
               "l"(Asrc + (arow) * 256 + (kc) * 64 + aseg * 8) : "memory"); \
        asm volatile("cp.async.cg.shared.global [%0], [%1], 16;" \
            :: "r"(sbm + (bo) + (u32)(((arow + 32) * ROWH + aseg * 8) * 2)), \
               "l"(Asrc + (arow + 32) * 256 + (kc) * 64 + aseg * 8) : "memory"); \
        _Pragma("unroll") \
        for (int t = 0; t < 8; ++t) { \
            int brow = t * 32 + (tid >> 3); \
            asm volatile("cp.async.cg.shared.global [%0], [%1], 16;" \
                :: "r"(sbm + (bo) + (u32)((G1_AH + brow * ROWH + aseg * 8) * 2)), \
                   "l"(g_woh + (size_t)brow * 256 + (kc) * 64 + aseg * 8) : "memory"); \
        } \
    } while (0)

    G1_PF(0, 0u);
    CP_COMMIT();

    for (int kc = 0; kc < 4; ++kc) {
        if (kc < 3) { G1_PF(kc + 1, (u32)(((kc + 1) & 1) * G1_BUF)); }
        CP_COMMIT();
        CP_WAIT(1);
        __syncthreads();
        const u32 base = sbm + (u32)((kc & 1) * G1_BUF);
        #pragma unroll
        for (int ks = 0; ks < 4; ++ks) {
            const u32 kb = (u32)(ks * 32);
            u32 A_[2][4], B_[4][4];
            #pragma unroll
            for (int m = 0; m < 2; ++m)
                LDM4(A_[m], base + aoff + m * (16 * ROWH * 2) + kb);
            #pragma unroll
            for (int p = 0; p < 4; ++p)
                LDM4(B_[p], base + boff + p * (16 * ROWH * 2) + kb);
            #pragma unroll
            for (int m = 0; m < 2; ++m)
                #pragma unroll
                for (int p = 0; p < 4; ++p)
                    #pragma unroll
                    for (int sub = 0; sub < 2; ++sub) {
                        u32 b2[2] = { B_[p][sub], B_[p][sub + 2] };
                        MMA16816(acc[m][p * 2 + sub], A_[m], b2);
                    }
        }
        __syncthreads();
    }

    // stage acc to smem fp32 [64][260]
    float* stage = (float*)smh;
    #pragma unroll
    for (int m = 0; m < 2; ++m) {
        int row = mw * 32 + m * 16 + gid;
        #pragma unroll
        for (int n = 0; n < 8; ++n) {
            int col = nw * 64 + n * 8 + tig * 2;
            *(float2*)(stage + row * 260 + col) = make_float2(acc[m][n][0], acc[m][n][1]);
            *(float2*)(stage + (row + 8) * 260 + col) = make_float2(acc[m][n][2], acc[m][n][3]);
        }
    }
    __syncthreads();

    const int tx = lane;
    for (int i = 0; i < 8; ++i) {
        int r = wid * 8 + i;
        int goff = row_goff(R + r);
        float v[8], s = 0.f, ss = 0.f;
        #pragma unroll
        for (int j = 0; j < 8; ++j) {
            int c = tx + 32 * j;
            v[j] = stage[r * 260 + c] + x[goff + c] + b_out[c];
            s += v[j]; ss += v[j] * v[j];
        }
        #pragma unroll
        for (int o = 16; o; o >>= 1) { s  += __shfl_xor_sync(0xffffffffu, s,  o);
                                       ss += __shfl_xor_sync(0xffffffffu, ss, o); }
        float mean = s * (1.f / 256.f);
        float inv  = rsqrtf(ss * (1.f / 256.f) - mean * mean + EPS);
        #pragma unroll
        for (int j = 0; j < 8; ++j) {
            int c = tx + 32 * j;
            y[goff + c] = (v[j] - mean) * inv * g_o[c] + b_o[c];
        }
    }
}

extern "C" void kernel_launch(void* const* d_in, const int* in_sizes, int n_in,
                              void* d_out, int out_size) {
    (void)in_sizes; (void)n_in; (void)out_size;
    const float* x     = (const float*)d_in[0];
    const float* w_in  = (const float*)d_in[1];
    const float* b_in  = (const float*)d_in[2];
    const float* w_out = (const float*)d_in[3];
    const float* b_out = (const float*)d_in[4];
    const float* g_q   = (const float*)d_in[5];
    const float* b_q   = (const float*)d_in[6];
    const float* g_k   = (const float*)d_in[7];
    const float* b_k   = (const float*)d_in[8];
    const float* g_v   = (const float*)d_in[9];
    const float* b_v   = (const float*)d_in[10];
    const float* g_o   = (const float*)d_in[11];
    const float* b_o   = (const float*)d_in[12];
    float* y = (float*)d_out;

    cudaFuncSetAttribute(gemm0_kernel, cudaFuncAttributeMaxDynamicSharedMemorySize, SMEM_G0);
    cudaFuncSetAttribute(attn_kernel, cudaFuncAttributeMaxDynamicSharedMemorySize, SMEM_ATTN);
    cudaFuncSetAttribute(gemm1_fused_kernel, cudaFuncAttributeMaxDynamicSharedMemorySize, SMEM_G1);

    prep_w_kernel<<<768, 256>>>(w_in, b_in, g_q, b_q, g_k, b_k, g_v, b_v);
    prep_wo_kernel<<<256, 256>>>(w_out);
    ln_split_kernel<<<MT / 8, 256>>>(x);
    gemm0_kernel<<<dim3(6, MT / 128), 256, SMEM_G0>>>();
    attn_kernel<<<2048, 256, SMEM_ATTN>>>();
    gemm1_fused_kernel<<<MT / 64, 256, SMEM_G1>>>(x, b_out, g_o, b_o, y);
}